// round 12
// baseline (speedup 1.0000x reference)
#include <cuda_runtime.h>
#include <cuda_bf16.h>
#include <cstdint>
#include <cstddef>

// Problem constants
#define B_SZ  4
#define S_LEN 2048
#define E_DIM 1024
#define NH    16
#define HD    64
#define M_TOT (B_SZ * S_LEN)   // 8192
#define N_TOT (3 * E_DIM)      // 3072
#define K_TOT E_DIM            // 1024

// ---------------------------------------------------------------------------
// Device-global scratch (no runtime allocation allowed)
// ---------------------------------------------------------------------------
__device__ float g_q[(size_t)B_SZ * NH * S_LEN * HD];
__device__ float g_k[(size_t)B_SZ * NH * S_LEN * HD];
__device__ float g_v[(size_t)B_SZ * NH * S_LEN * HD];

// bf16 hi/lo splits: x as [M,K], W^T as [N,K]
__device__ __nv_bfloat16 g_xhi[(size_t)M_TOT * K_TOT];
__device__ __nv_bfloat16 g_xlo[(size_t)M_TOT * K_TOT];
__device__ __nv_bfloat16 g_wthi[(size_t)N_TOT * K_TOT];
__device__ __nv_bfloat16 g_wtlo[(size_t)N_TOT * K_TOT];

// ---------------------------------------------------------------------------
// f32x2 helpers (attention kernel)
// ---------------------------------------------------------------------------
__device__ __forceinline__ unsigned long long dup2(float x) {
    unsigned long long r;
    unsigned u = __float_as_uint(x);
    asm("mov.b64 %0, {%1, %1};" : "=l"(r) : "r"(u));
    return r;
}
__device__ __forceinline__ void fma2(unsigned long long& acc,
                                     unsigned long long a, unsigned long long b) {
    asm("fma.rn.f32x2 %0, %1, %2, %0;" : "+l"(acc) : "l"(a), "l"(b));
}
__device__ __forceinline__ void mul2(unsigned long long& acc, unsigned long long a) {
    asm("mul.rn.f32x2 %0, %0, %1;" : "+l"(acc) : "l"(a));
}
__device__ __forceinline__ float2 unpk(unsigned long long v) {
    unsigned lo, hi;
    asm("mov.b64 {%0, %1}, %2;" : "=r"(lo), "=r"(hi) : "l"(v));
    return make_float2(__uint_as_float(lo), __uint_as_float(hi));
}

// ---------------------------------------------------------------------------
// mma.sync / ldmatrix / cp.async helpers (baseline PTX, valid on sm_103)
// ---------------------------------------------------------------------------
__device__ __forceinline__ uint32_t smem_u32(const void* p) {
    uint32_t a;
    asm("{ .reg .u64 t; cvta.to.shared.u64 t, %1; cvt.u32.u64 %0, t; }"
        : "=r"(a) : "l"(p));
    return a;
}
__device__ __forceinline__ void ldm_x4(uint32_t* r, uint32_t addr) {
    asm volatile("ldmatrix.sync.aligned.m8n8.x4.shared.b16 {%0,%1,%2,%3}, [%4];"
                 : "=r"(r[0]), "=r"(r[1]), "=r"(r[2]), "=r"(r[3]) : "r"(addr));
}
__device__ __forceinline__ void mma16816(float* c, const uint32_t* a,
                                         uint32_t b0, uint32_t b1) {
    asm volatile(
        "mma.sync.aligned.m16n8k16.row.col.f32.bf16.bf16.f32 "
        "{%0,%1,%2,%3}, {%4,%5,%6,%7}, {%8,%9}, {%0,%1,%2,%3};"
        : "+f"(c[0]), "+f"(c[1]), "+f"(c[2]), "+f"(c[3])
        : "r"(a[0]), "r"(a[1]), "r"(a[2]), "r"(a[3]), "r"(b0), "r"(b1));
}
__device__ __forceinline__ void cp_async16(uint32_t saddr, const void* gaddr) {
    asm volatile("cp.async.cg.shared.global [%0], [%1], 16;"
                 :: "r"(saddr), "l"(gaddr));
}
#define CP_COMMIT() asm volatile("cp.async.commit_group;" ::: "memory")
#define CP_WAIT2()  asm volatile("cp.async.wait_group 2;" ::: "memory")

// ---------------------------------------------------------------------------
// Split pre-pass kernels: fp32 -> bf16 hi/lo
// ---------------------------------------------------------------------------
__global__ __launch_bounds__(256) void split_x(const float* __restrict__ x) {
    size_t i = ((size_t)blockIdx.x * 256 + threadIdx.x) * 4;
    float4 v = *(const float4*)(x + i);
    __nv_bfloat16 h0 = __float2bfloat16(v.x), h1 = __float2bfloat16(v.y);
    __nv_bfloat16 h2 = __float2bfloat16(v.z), h3 = __float2bfloat16(v.w);
    __nv_bfloat16 l0 = __float2bfloat16(v.x - __bfloat162float(h0));
    __nv_bfloat16 l1 = __float2bfloat16(v.y - __bfloat162float(h1));
    __nv_bfloat16 l2 = __float2bfloat16(v.z - __bfloat162float(h2));
    __nv_bfloat16 l3 = __float2bfloat16(v.w - __bfloat162float(h3));
    *(ushort4*)(g_xhi + i) = make_ushort4(
        __bfloat16_as_ushort(h0), __bfloat16_as_ushort(h1),
        __bfloat16_as_ushort(h2), __bfloat16_as_ushort(h3));
    *(ushort4*)(g_xlo + i) = make_ushort4(
        __bfloat16_as_ushort(l0), __bfloat16_as_ushort(l1),
        __bfloat16_as_ushort(l2), __bfloat16_as_ushort(l3));
}

// transpose W [K,N] -> W^T [N,K] with split (L2 catches the line re-reads)
__global__ __launch_bounds__(256) void split_wt(const float* __restrict__ w) {
    const int n = blockIdx.x;              // 0..3071
    const int k0 = threadIdx.x * 4;        // 0..1020
    float v[4];
#pragma unroll
    for (int j = 0; j < 4; j++) v[j] = w[(size_t)(k0 + j) * N_TOT + n];
    unsigned short hh[4], ll[4];
#pragma unroll
    for (int j = 0; j < 4; j++) {
        __nv_bfloat16 h = __float2bfloat16(v[j]);
        __nv_bfloat16 l = __float2bfloat16(v[j] - __bfloat162float(h));
        hh[j] = __bfloat16_as_ushort(h);
        ll[j] = __bfloat16_as_ushort(l);
    }
    *(ushort4*)(g_wthi + (size_t)n * K_TOT + k0) = make_ushort4(hh[0], hh[1], hh[2], hh[3]);
    *(ushort4*)(g_wtlo + (size_t)n * K_TOT + k0) = make_ushort4(ll[0], ll[1], ll[2], ll[3]);
}

// ---------------------------------------------------------------------------
// QKV GEMM via mma.sync bf16 (error-compensated split):
//   D = Ah.Bh + Ah.Bl + Al.Bh,  fp32 accum.
// 128x128 CTA tile, BK=64 (128B rows, SW128 swizzle), 8 warps (4x2 grid,
// 32x64 warp tile), 3-stage cp.async pipeline.
// ---------------------------------------------------------------------------
#define BKC    64
#define NCHUNK (K_TOT / BKC)     // 16
#define OPBYTES (128 * 128)      // 16384: 128 rows x 128B
#define STB    (4 * OPBYTES)     // 65536 per stage (Ah, Al, Bh, Bl)
#define GSM    (3 * STB)         // 196608 dynamic smem

__global__ __launch_bounds__(256, 1) void qkv_mma() {
    extern __shared__ char sm[];
    const int tid = threadIdx.x;
    const int lane = tid & 31;
    const int w = tid >> 5;
    const int wr = w & 3, wc = w >> 2;       // 4x2 warp grid
    const int wm0 = wr * 32, wn0 = wc * 64;
    const int m0 = (int)blockIdx.y << 7;
    const int n0 = (int)blockIdx.x << 7;
    const uint32_t smb = smem_u32(sm);

    const __nv_bfloat16* srcs[4] = {
        g_xhi + (size_t)m0 * K_TOT, g_xlo + (size_t)m0 * K_TOT,
        g_wthi + (size_t)n0 * K_TOT, g_wtlo + (size_t)n0 * K_TOT };

    auto issue_stage = [&](int buf, int kc) {
        const int koff = kc * BKC;
#pragma unroll
        for (int op = 0; op < 4; op++) {
            const uint32_t sb = smb + buf * STB + op * OPBYTES;
            const __nv_bfloat16* gp = srcs[op] + koff;
#pragma unroll
            for (int t = 0; t < 4; t++) {
                const int idx = tid + t * 256;
                const int row = idx >> 3, seg = idx & 7;
                uint32_t off = (uint32_t)(row * 128 + seg * 16);
                off ^= (off >> 3) & 0x70;              // SW128 swizzle
                cp_async16(sb + off, gp + (size_t)row * K_TOT + seg * 8);
            }
        }
    };

    float acc[2][8][4];
#pragma unroll
    for (int i = 0; i < 2; i++)
#pragma unroll
        for (int j = 0; j < 8; j++)
#pragma unroll
            for (int q = 0; q < 4; q++) acc[i][j][q] = 0.0f;

    issue_stage(0, 0); CP_COMMIT();
    issue_stage(1, 1); CP_COMMIT();

    for (int c = 0; c < NCHUNK; c++) {
        if (c + 2 < NCHUNK) issue_stage((c + 2) % 3, c + 2);
        CP_COMMIT();                 // always commit (keeps group count uniform)
        CP_WAIT2();                  // stage c complete
        __syncthreads();

        const uint32_t ab = smb + (c % 3) * STB;
        const uint32_t alb = ab + OPBYTES;
        const uint32_t bhb = ab + 2 * OPBYTES;
        const uint32_t blb = ab + 3 * OPBYTES;

#pragma unroll
        for (int ks = 0; ks < 4; ks++) {
            uint32_t ah[2][4], al[2][4];
#pragma unroll
            for (int mi = 0; mi < 2; mi++) {
                const int row = wm0 + mi * 16 + (lane & 15);
                const int seg = ks * 2 + (lane >> 4);
                const uint32_t off = row * 128 + (((seg ^ (row & 7)) & 7) << 4);
                ldm_x4(ah[mi], ab + off);
                ldm_x4(al[mi], alb + off);
            }
            uint32_t bh[4][4], bl[4][4];
#pragma unroll
            for (int nf = 0; nf < 4; nf++) {
                const int row = wn0 + nf * 16 + (lane & 7) + ((lane >> 4) << 3);
                const int seg = ks * 2 + ((lane >> 3) & 1);
                const uint32_t off = row * 128 + (((seg ^ (row & 7)) & 7) << 4);
                ldm_x4(bh[nf], bhb + off);
                ldm_x4(bl[nf], blb + off);
            }
#pragma unroll
            for (int mi = 0; mi < 2; mi++)
#pragma unroll
                for (int nf = 0; nf < 4; nf++) {
                    mma16816(acc[mi][2 * nf],     ah[mi], bh[nf][0], bh[nf][1]);
                    mma16816(acc[mi][2 * nf + 1], ah[mi], bh[nf][2], bh[nf][3]);
                    mma16816(acc[mi][2 * nf],     ah[mi], bl[nf][0], bl[nf][1]);
                    mma16816(acc[mi][2 * nf + 1], ah[mi], bl[nf][2], bl[nf][3]);
                    mma16816(acc[mi][2 * nf],     al[mi], bh[nf][0], bh[nf][1]);
                    mma16816(acc[mi][2 * nf + 1], al[mi], bh[nf][2], bh[nf][3]);
                }
        }
        __syncthreads();   // all reads of buf done before it is refilled
    }

    // epilogue: scatter warp's 32x64 C tile into [B,H,S,D] Q/K/V
    const int qr = lane >> 2;
    const int qc = (lane & 3) << 1;
    const int bb = m0 >> 11;                 // whole tile in one batch
    const int ncol0 = n0 + wn0;              // 64-aligned -> one (which, head)
    const int which = ncol0 >> 10;
    const int h = (ncol0 >> 6) & (NH - 1);
    float* basep = (which == 0 ? g_q : which == 1 ? g_k : g_v)
                   + ((size_t)(bb * NH + h)) * S_LEN * HD;
    const float sc = (which == 0) ? 0.125f : 1.0f;   // fold 1/sqrt(D) into Q
    const int s00 = (m0 & (S_LEN - 1)) + wm0;

#pragma unroll
    for (int mi = 0; mi < 2; mi++)
#pragma unroll
        for (int nf8 = 0; nf8 < 8; nf8++) {
            const int d = nf8 * 8 + qc;
            const int s0 = s00 + mi * 16 + qr;
            float2 v0 = make_float2(acc[mi][nf8][0] * sc, acc[mi][nf8][1] * sc);
            float2 v1 = make_float2(acc[mi][nf8][2] * sc, acc[mi][nf8][3] * sc);
            *(float2*)(basep + (size_t)s0 * HD + d) = v0;
            *(float2*)(basep + (size_t)(s0 + 8) * HD + d) = v1;
        }
}

// ============================================================================
// Kernel 2: causal flash attention, fp32, f32x2 packed FMA (UNCHANGED)
// ============================================================================
__global__ __launch_bounds__(256, 2) void attn_kernel(float* __restrict__ out) {
    __shared__ float Qs[64 * 64];    // [r][d]
    __shared__ float KPs[64 * 64];   // K^T swizzled [d][c], then P [r][c]
    __shared__ float Vs[64 * 64];    // [c][d]

    const int tid = threadIdx.x;
    const int tx = tid & 15, ty = tid >> 4;
    const int qtile = (int)gridDim.x - 1 - (int)blockIdx.x;  // long blocks first
    const int bh = blockIdx.y;
    const int qbase = qtile << 6;
    const float NEG_INF = __int_as_float(0xff800000);

    const float* Qg = g_q + (size_t)bh * S_LEN * HD;
    const float* Kg = g_k + (size_t)bh * S_LEN * HD;
    const float* Vg = g_v + (size_t)bh * S_LEN * HD;

    const int lr = tid >> 2;   // 0..63 (row)
    const int lv = tid & 3;    // 0..3  (vec)

#pragma unroll
    for (int c = 0; c < 4; c++) {
        const int dv = lv + (c << 2);
        *(float4*)&Qs[lr * 64 + (dv << 2)] =
            *(const float4*)(Qg + (size_t)(qbase + lr) * HD + (dv << 2));
    }

    float mrow[4], lrow[4];
    unsigned long long oacc[4][2];
#pragma unroll
    for (int i = 0; i < 4; i++) {
        mrow[i] = NEG_INF; lrow[i] = 0.0f;
        oacc[i][0] = 0ULL; oacc[i][1] = 0ULL;
    }

    for (int kt = 0; kt <= qtile; kt++) {
        const int kbase = kt << 6;
        __syncthreads();

#pragma unroll
        for (int c = 0; c < 4; c++) {
            const int dv = lv + (c << 2);
            const int d0 = dv << 2;
            float4 kv = *(const float4*)(Kg + (size_t)(kbase + lr) * HD + d0);
            const int q = lr >> 2, lo = lr & 3;
            KPs[(d0 + 0) * 64 + ((q ^ ((d0 + 0) & 15)) << 2) + lo] = kv.x;
            KPs[(d0 + 1) * 64 + ((q ^ ((d0 + 1) & 15)) << 2) + lo] = kv.y;
            KPs[(d0 + 2) * 64 + ((q ^ ((d0 + 2) & 15)) << 2) + lo] = kv.z;
            KPs[(d0 + 3) * 64 + ((q ^ ((d0 + 3) & 15)) << 2) + lo] = kv.w;
            *(float4*)&Vs[lr * 64 + d0] =
                *(const float4*)(Vg + (size_t)(kbase + lr) * HD + d0);
        }
        __syncthreads();

        unsigned long long sc2[4][2];
#pragma unroll
        for (int i = 0; i < 4; i++) { sc2[i][0] = 0ULL; sc2[i][1] = 0ULL; }

#pragma unroll
        for (int d0 = 0; d0 < 64; d0 += 4) {
            float4 af[4];
#pragma unroll
            for (int i = 0; i < 4; i++)
                af[i] = *(float4*)&Qs[((ty << 2) + i) * 64 + d0];
            unsigned long long bf[4][2];
#pragma unroll
            for (int dd = 0; dd < 4; dd++) {
                const int d = d0 + dd;
                ulonglong2 t = *(ulonglong2*)&KPs[d * 64 + ((tx ^ (d & 15)) << 2)];
                bf[dd][0] = t.x; bf[dd][1] = t.y;
            }
#pragma unroll
            for (int i = 0; i < 4; i++) {
                unsigned long long a0 = dup2(af[i].x), a1 = dup2(af[i].y);
                unsigned long long a2 = dup2(af[i].z), a3 = dup2(af[i].w);
                fma2(sc2[i][0], a0, bf[0][0]); fma2(sc2[i][1], a0, bf[0][1]);
                fma2(sc2[i][0], a1, bf[1][0]); fma2(sc2[i][1], a1, bf[1][1]);
                fma2(sc2[i][0], a2, bf[2][0]); fma2(sc2[i][1], a2, bf[2][1]);
                fma2(sc2[i][0], a3, bf[3][0]); fma2(sc2[i][1], a3, bf[3][1]);
            }
        }

        const bool diag = (kt == qtile);
        float pfrag[4][4];
#pragma unroll
        for (int i = 0; i < 4; i++) {
            float2 p01 = unpk(sc2[i][0]);
            float2 p23 = unpk(sc2[i][1]);
            float s0 = p01.x, s1 = p01.y, s2 = p23.x, s3 = p23.y;
            if (diag) {
                const int rg = qbase + (ty << 2) + i;
                const int cg = kbase + (tx << 2);
                if (cg + 0 > rg) s0 = NEG_INF;
                if (cg + 1 > rg) s1 = NEG_INF;
                if (cg + 2 > rg) s2 = NEG_INF;
                if (cg + 3 > rg) s3 = NEG_INF;
            }
            float rmax = fmaxf(fmaxf(s0, s1), fmaxf(s2, s3));
#pragma unroll
            for (int o = 8; o >= 1; o >>= 1)
                rmax = fmaxf(rmax, __shfl_xor_sync(0xffffffffu, rmax, o, 16));
            const float mnew = fmaxf(mrow[i], rmax);
            const float alpha = __expf(mrow[i] - mnew);
            const float p0 = __expf(s0 - mnew);
            const float p1 = __expf(s1 - mnew);
            const float p2 = __expf(s2 - mnew);
            const float p3 = __expf(s3 - mnew);
            float rsum = (p0 + p1) + (p2 + p3);
#pragma unroll
            for (int o = 8; o >= 1; o >>= 1)
                rsum += __shfl_xor_sync(0xffffffffu, rsum, o, 16);
            lrow[i] = lrow[i] * alpha + rsum;
            mrow[i] = mnew;
            unsigned long long al2 = dup2(alpha);
            mul2(oacc[i][0], al2);
            mul2(oacc[i][1], al2);
            pfrag[i][0] = p0; pfrag[i][1] = p1; pfrag[i][2] = p2; pfrag[i][3] = p3;
        }

        __syncthreads();
#pragma unroll
        for (int i = 0; i < 4; i++)
            *(float4*)&KPs[((ty << 2) + i) * 64 + (tx << 2)] = *(float4*)&pfrag[i][0];
        __syncthreads();

#pragma unroll
        for (int c0 = 0; c0 < 64; c0 += 4) {
            float4 pf[4];
#pragma unroll
            for (int i = 0; i < 4; i++)
                pf[i] = *(float4*)&KPs[((ty << 2) + i) * 64 + c0];
            unsigned long long vf[4][2];
#pragma unroll
            for (int k = 0; k < 4; k++) {
                ulonglong2 t = *(ulonglong2*)&Vs[(c0 + k) * 64 + (tx << 2)];
                vf[k][0] = t.x; vf[k][1] = t.y;
            }
#pragma unroll
            for (int i = 0; i < 4; i++) {
                unsigned long long p0 = dup2(pf[i].x), p1 = dup2(pf[i].y);
                unsigned long long p2 = dup2(pf[i].z), p3 = dup2(pf[i].w);
                fma2(oacc[i][0], p0, vf[0][0]); fma2(oacc[i][1], p0, vf[0][1]);
                fma2(oacc[i][0], p1, vf[1][0]); fma2(oacc[i][1], p1, vf[1][1]);
                fma2(oacc[i][0], p2, vf[2][0]); fma2(oacc[i][1], p2, vf[2][1]);
                fma2(oacc[i][0], p3, vf[3][0]); fma2(oacc[i][1], p3, vf[3][1]);
            }
        }
    }

    const int b = bh >> 4, h = bh & 15;
#pragma unroll
    for (int i = 0; i < 4; i++) {
        const int s = qbase + (ty << 2) + i;
        const float inv = 1.0f / lrow[i];
        float2 o01 = unpk(oacc[i][0]);
        float2 o23 = unpk(oacc[i][1]);
        float4 o4 = make_float4(o01.x * inv, o01.y * inv, o23.x * inv, o23.y * inv);
        *(float4*)(out + ((size_t)b * S_LEN + s) * E_DIM + h * HD + (tx << 2)) = o4;
    }
}

// ============================================================================
// Launch
// ============================================================================
extern "C" void kernel_launch(void* const* d_in, const int* in_sizes, int n_in,
                              void* d_out, int out_size) {
    (void)in_sizes; (void)n_in; (void)out_size;
    const float* x = (const float*)d_in[0];   // [4,2048,1024] fp32
    const float* w = (const float*)d_in[1];   // [1024,3072] fp32
    float* out = (float*)d_out;               // [4,2048,1024] fp32

    static int smem_set = 0;
    if (!smem_set) {
        cudaFuncSetAttribute(qkv_mma,
                             cudaFuncAttributeMaxDynamicSharedMemorySize, GSM);
        smem_set = 1;
    }

    split_x<<<(size_t)M_TOT * K_TOT / 4 / 256, 256>>>(x);   // 8192 blocks
    split_wt<<<N_TOT, 256>>>(w);                            // 3072 blocks
    qkv_mma<<<dim3(N_TOT / 128, M_TOT / 128), 256, GSM>>>();
    attn_kernel<<<dim3(S_LEN / 64, B_SZ * NH), 256>>>(out);
}

// round 13
// speedup vs baseline: 1.5951x; 1.5951x over previous
#include <cuda_runtime.h>
#include <cuda_bf16.h>
#include <cstdint>
#include <cstddef>

// Problem constants
#define B_SZ  4
#define S_LEN 2048
#define E_DIM 1024
#define NH    16
#define HD    64
#define M_TOT (B_SZ * S_LEN)   // 8192
#define N_TOT (3 * E_DIM)      // 3072
#define K_TOT E_DIM            // 1024

// ---------------------------------------------------------------------------
// Device-global scratch (no runtime allocation allowed)
// ---------------------------------------------------------------------------
__device__ float g_q[(size_t)B_SZ * NH * S_LEN * HD];
__device__ float g_k[(size_t)B_SZ * NH * S_LEN * HD];
__device__ float g_v[(size_t)B_SZ * NH * S_LEN * HD];

// bf16 hi/lo splits: x as [M,K], W^T as [N,K]
__device__ __nv_bfloat16 g_xhi[(size_t)M_TOT * K_TOT];
__device__ __nv_bfloat16 g_xlo[(size_t)M_TOT * K_TOT];
__device__ __nv_bfloat16 g_wthi[(size_t)N_TOT * K_TOT];
__device__ __nv_bfloat16 g_wtlo[(size_t)N_TOT * K_TOT];

// ---------------------------------------------------------------------------
// f32x2 helpers (attention kernel)
// ---------------------------------------------------------------------------
__device__ __forceinline__ unsigned long long dup2(float x) {
    unsigned long long r;
    unsigned u = __float_as_uint(x);
    asm("mov.b64 %0, {%1, %1};" : "=l"(r) : "r"(u));
    return r;
}
__device__ __forceinline__ void fma2(unsigned long long& acc,
                                     unsigned long long a, unsigned long long b) {
    asm("fma.rn.f32x2 %0, %1, %2, %0;" : "+l"(acc) : "l"(a), "l"(b));
}
__device__ __forceinline__ void mul2(unsigned long long& acc, unsigned long long a) {
    asm("mul.rn.f32x2 %0, %0, %1;" : "+l"(acc) : "l"(a));
}
__device__ __forceinline__ float2 unpk(unsigned long long v) {
    unsigned lo, hi;
    asm("mov.b64 {%0, %1}, %2;" : "=r"(lo), "=r"(hi) : "l"(v));
    return make_float2(__uint_as_float(lo), __uint_as_float(hi));
}

// ---------------------------------------------------------------------------
// mma.sync / ldmatrix / cp.async helpers (baseline PTX, valid on sm_103)
// ---------------------------------------------------------------------------
__device__ __forceinline__ uint32_t smem_u32(const void* p) {
    uint32_t a;
    asm("{ .reg .u64 t; cvta.to.shared.u64 t, %1; cvt.u32.u64 %0, t; }"
        : "=r"(a) : "l"(p));
    return a;
}
__device__ __forceinline__ void ldm_x4(uint32_t* r, uint32_t addr) {
    asm volatile("ldmatrix.sync.aligned.m8n8.x4.shared.b16 {%0,%1,%2,%3}, [%4];"
                 : "=r"(r[0]), "=r"(r[1]), "=r"(r[2]), "=r"(r[3]) : "r"(addr));
}
__device__ __forceinline__ void mma16816(float* c, const uint32_t* a,
                                         uint32_t b0, uint32_t b1) {
    asm volatile(
        "mma.sync.aligned.m16n8k16.row.col.f32.bf16.bf16.f32 "
        "{%0,%1,%2,%3}, {%4,%5,%6,%7}, {%8,%9}, {%0,%1,%2,%3};"
        : "+f"(c[0]), "+f"(c[1]), "+f"(c[2]), "+f"(c[3])
        : "r"(a[0]), "r"(a[1]), "r"(a[2]), "r"(a[3]), "r"(b0), "r"(b1));
}
__device__ __forceinline__ void cp_async16(uint32_t saddr, const void* gaddr) {
    asm volatile("cp.async.cg.shared.global [%0], [%1], 16;"
                 :: "r"(saddr), "l"(gaddr));
}
#define CP_COMMIT() asm volatile("cp.async.commit_group;" ::: "memory")
#define CP_WAIT2()  asm volatile("cp.async.wait_group 2;" ::: "memory")

// ---------------------------------------------------------------------------
// Split pre-pass kernels: fp32 -> bf16 hi/lo
// ---------------------------------------------------------------------------
__global__ __launch_bounds__(256) void split_x(const float* __restrict__ x) {
    size_t i = ((size_t)blockIdx.x * 256 + threadIdx.x) * 4;
    float4 v = *(const float4*)(x + i);
    __nv_bfloat16 h0 = __float2bfloat16(v.x), h1 = __float2bfloat16(v.y);
    __nv_bfloat16 h2 = __float2bfloat16(v.z), h3 = __float2bfloat16(v.w);
    __nv_bfloat16 l0 = __float2bfloat16(v.x - __bfloat162float(h0));
    __nv_bfloat16 l1 = __float2bfloat16(v.y - __bfloat162float(h1));
    __nv_bfloat16 l2 = __float2bfloat16(v.z - __bfloat162float(h2));
    __nv_bfloat16 l3 = __float2bfloat16(v.w - __bfloat162float(h3));
    *(ushort4*)(g_xhi + i) = make_ushort4(
        __bfloat16_as_ushort(h0), __bfloat16_as_ushort(h1),
        __bfloat16_as_ushort(h2), __bfloat16_as_ushort(h3));
    *(ushort4*)(g_xlo + i) = make_ushort4(
        __bfloat16_as_ushort(l0), __bfloat16_as_ushort(l1),
        __bfloat16_as_ushort(l2), __bfloat16_as_ushort(l3));
}

// transpose W [K,N] -> W^T [N,K] with split (L2 catches the line re-reads)
__global__ __launch_bounds__(256) void split_wt(const float* __restrict__ w) {
    const int n = blockIdx.x;              // 0..3071
    const int k0 = threadIdx.x * 4;        // 0..1020
    float v[4];
#pragma unroll
    for (int j = 0; j < 4; j++) v[j] = w[(size_t)(k0 + j) * N_TOT + n];
    unsigned short hh[4], ll[4];
#pragma unroll
    for (int j = 0; j < 4; j++) {
        __nv_bfloat16 h = __float2bfloat16(v[j]);
        __nv_bfloat16 l = __float2bfloat16(v[j] - __bfloat162float(h));
        hh[j] = __bfloat16_as_ushort(h);
        ll[j] = __bfloat16_as_ushort(l);
    }
    *(ushort4*)(g_wthi + (size_t)n * K_TOT + k0) = make_ushort4(hh[0], hh[1], hh[2], hh[3]);
    *(ushort4*)(g_wtlo + (size_t)n * K_TOT + k0) = make_ushort4(ll[0], ll[1], ll[2], ll[3]);
}

// ---------------------------------------------------------------------------
// QKV GEMM via mma.sync bf16 (error-compensated split):
//   D = Ah.Bh + Ah.Bl + Al.Bh,  fp32 accum.
// 128x128 CTA tile, BK=64 (128B rows, SW128 swizzle), 8 warps (4x2 grid,
// 32x64 warp tile), 3-stage cp.async pipeline.
// ---------------------------------------------------------------------------
#define BKC    64
#define NCHUNK (K_TOT / BKC)     // 16
#define OPBYTES (128 * 128)      // 16384: 128 rows x 128B
#define STB    (4 * OPBYTES)     // 65536 per stage (Ah, Al, Bh, Bl)
#define GSM    (3 * STB)         // 196608 dynamic smem

__global__ __launch_bounds__(256, 1) void qkv_mma() {
    extern __shared__ char sm[];
    const int tid = threadIdx.x;
    const int lane = tid & 31;
    const int w = tid >> 5;
    const int wr = w & 3, wc = w >> 2;       // 4x2 warp grid
    const int wm0 = wr * 32, wn0 = wc * 64;
    const int m0 = (int)blockIdx.y << 7;
    const int n0 = (int)blockIdx.x << 7;
    const uint32_t smb = smem_u32(sm);

    const __nv_bfloat16* srcs[4] = {
        g_xhi + (size_t)m0 * K_TOT, g_xlo + (size_t)m0 * K_TOT,
        g_wthi + (size_t)n0 * K_TOT, g_wtlo + (size_t)n0 * K_TOT };

    auto issue_stage = [&](int buf, int kc) {
        const int koff = kc * BKC;
#pragma unroll
        for (int op = 0; op < 4; op++) {
            const uint32_t sb = smb + buf * STB + op * OPBYTES;
            const __nv_bfloat16* gp = srcs[op] + koff;
#pragma unroll
            for (int t = 0; t < 4; t++) {
                const int idx = tid + t * 256;
                const int row = idx >> 3, seg = idx & 7;
                uint32_t off = (uint32_t)(row * 128 + seg * 16);
                off ^= (off >> 3) & 0x70;              // SW128 swizzle
                cp_async16(sb + off, gp + (size_t)row * K_TOT + seg * 8);
            }
        }
    };

    float acc[2][8][4];
#pragma unroll
    for (int i = 0; i < 2; i++)
#pragma unroll
        for (int j = 0; j < 8; j++)
#pragma unroll
            for (int q = 0; q < 4; q++) acc[i][j][q] = 0.0f;

    issue_stage(0, 0); CP_COMMIT();
    issue_stage(1, 1); CP_COMMIT();

    for (int c = 0; c < NCHUNK; c++) {
        if (c + 2 < NCHUNK) issue_stage((c + 2) % 3, c + 2);
        CP_COMMIT();                 // always commit (keeps group count uniform)
        CP_WAIT2();                  // stage c complete
        __syncthreads();

        const uint32_t ab = smb + (c % 3) * STB;
        const uint32_t alb = ab + OPBYTES;
        const uint32_t bhb = ab + 2 * OPBYTES;
        const uint32_t blb = ab + 3 * OPBYTES;

#pragma unroll
        for (int ks = 0; ks < 4; ks++) {
            uint32_t ah[2][4], al[2][4];
#pragma unroll
            for (int mi = 0; mi < 2; mi++) {
                const int row = wm0 + mi * 16 + (lane & 15);
                const int seg = ks * 2 + (lane >> 4);
                const uint32_t off = row * 128 + (((seg ^ (row & 7)) & 7) << 4);
                ldm_x4(ah[mi], ab + off);
                ldm_x4(al[mi], alb + off);
            }
            uint32_t bh[4][4], bl[4][4];
#pragma unroll
            for (int nf = 0; nf < 4; nf++) {
                const int row = wn0 + nf * 16 + (lane & 7) + ((lane >> 4) << 3);
                const int seg = ks * 2 + ((lane >> 3) & 1);
                const uint32_t off = row * 128 + (((seg ^ (row & 7)) & 7) << 4);
                ldm_x4(bh[nf], bhb + off);
                ldm_x4(bl[nf], blb + off);
            }
#pragma unroll
            for (int mi = 0; mi < 2; mi++)
#pragma unroll
                for (int nf = 0; nf < 4; nf++) {
                    mma16816(acc[mi][2 * nf],     ah[mi], bh[nf][0], bh[nf][1]);
                    mma16816(acc[mi][2 * nf + 1], ah[mi], bh[nf][2], bh[nf][3]);
                    mma16816(acc[mi][2 * nf],     ah[mi], bl[nf][0], bl[nf][1]);
                    mma16816(acc[mi][2 * nf + 1], ah[mi], bl[nf][2], bl[nf][3]);
                    mma16816(acc[mi][2 * nf],     al[mi], bh[nf][0], bh[nf][1]);
                    mma16816(acc[mi][2 * nf + 1], al[mi], bh[nf][2], bh[nf][3]);
                }
        }
        __syncthreads();   // all reads of buf done before it is refilled
    }

    // epilogue: scatter warp's 32x64 C tile into [B,H,S,D] Q/K/V
    const int qr = lane >> 2;
    const int qc = (lane & 3) << 1;
    const int bb = m0 >> 11;                 // whole tile in one batch
    const int ncol0 = n0 + wn0;              // 64-aligned -> one (which, head)
    const int which = ncol0 >> 10;
    const int h = (ncol0 >> 6) & (NH - 1);
    float* basep = (which == 0 ? g_q : which == 1 ? g_k : g_v)
                   + ((size_t)(bb * NH + h)) * S_LEN * HD;
    const float sc = (which == 0) ? 0.125f : 1.0f;   // fold 1/sqrt(D) into Q
    const int s00 = (m0 & (S_LEN - 1)) + wm0;

#pragma unroll
    for (int mi = 0; mi < 2; mi++)
#pragma unroll
        for (int nf8 = 0; nf8 < 8; nf8++) {
            const int d = nf8 * 8 + qc;
            const int s0 = s00 + mi * 16 + qr;
            float2 v0 = make_float2(acc[mi][nf8][0] * sc, acc[mi][nf8][1] * sc);
            float2 v1 = make_float2(acc[mi][nf8][2] * sc, acc[mi][nf8][3] * sc);
            *(float2*)(basep + (size_t)s0 * HD + d) = v0;
            *(float2*)(basep + (size_t)(s0 + 8) * HD + d) = v1;
        }
}

// ============================================================================
// Kernel 2: causal flash attention, fp32, f32x2 packed FMA (UNCHANGED)
// ============================================================================
__global__ __launch_bounds__(256, 2) void attn_kernel(float* __restrict__ out) {
    __shared__ float Qs[64 * 64];    // [r][d]
    __shared__ float KPs[64 * 64];   // K^T swizzled [d][c], then P [r][c]
    __shared__ float Vs[64 * 64];    // [c][d]

    const int tid = threadIdx.x;
    const int tx = tid & 15, ty = tid >> 4;
    const int qtile = (int)gridDim.x - 1 - (int)blockIdx.x;  // long blocks first
    const int bh = blockIdx.y;
    const int qbase = qtile << 6;
    const float NEG_INF = __int_as_float(0xff800000);

    const float* Qg = g_q + (size_t)bh * S_LEN * HD;
    const float* Kg = g_k + (size_t)bh * S_LEN * HD;
    const float* Vg = g_v + (size_t)bh * S_LEN * HD;

    const int lr = tid >> 2;   // 0..63 (row)
    const int lv = tid & 3;    // 0..3  (vec)

#pragma unroll
    for (int c = 0; c < 4; c++) {
        const int dv = lv + (c << 2);
        *(float4*)&Qs[lr * 64 + (dv << 2)] =
            *(const float4*)(Qg + (size_t)(qbase + lr) * HD + (dv << 2));
    }

    float mrow[4], lrow[4];
    unsigned long long oacc[4][2];
#pragma unroll
    for (int i = 0; i < 4; i++) {
        mrow[i] = NEG_INF; lrow[i] = 0.0f;
        oacc[i][0] = 0ULL; oacc[i][1] = 0ULL;
    }

    for (int kt = 0; kt <= qtile; kt++) {
        const int kbase = kt << 6;
        __syncthreads();

#pragma unroll
        for (int c = 0; c < 4; c++) {
            const int dv = lv + (c << 2);
            const int d0 = dv << 2;
            float4 kv = *(const float4*)(Kg + (size_t)(kbase + lr) * HD + d0);
            const int q = lr >> 2, lo = lr & 3;
            KPs[(d0 + 0) * 64 + ((q ^ ((d0 + 0) & 15)) << 2) + lo] = kv.x;
            KPs[(d0 + 1) * 64 + ((q ^ ((d0 + 1) & 15)) << 2) + lo] = kv.y;
            KPs[(d0 + 2) * 64 + ((q ^ ((d0 + 2) & 15)) << 2) + lo] = kv.z;
            KPs[(d0 + 3) * 64 + ((q ^ ((d0 + 3) & 15)) << 2) + lo] = kv.w;
            *(float4*)&Vs[lr * 64 + d0] =
                *(const float4*)(Vg + (size_t)(kbase + lr) * HD + d0);
        }
        __syncthreads();

        unsigned long long sc2[4][2];
#pragma unroll
        for (int i = 0; i < 4; i++) { sc2[i][0] = 0ULL; sc2[i][1] = 0ULL; }

#pragma unroll
        for (int d0 = 0; d0 < 64; d0 += 4) {
            float4 af[4];
#pragma unroll
            for (int i = 0; i < 4; i++)
                af[i] = *(float4*)&Qs[((ty << 2) + i) * 64 + d0];
            unsigned long long bf[4][2];
#pragma unroll
            for (int dd = 0; dd < 4; dd++) {
                const int d = d0 + dd;
                ulonglong2 t = *(ulonglong2*)&KPs[d * 64 + ((tx ^ (d & 15)) << 2)];
                bf[dd][0] = t.x; bf[dd][1] = t.y;
            }
#pragma unroll
            for (int i = 0; i < 4; i++) {
                unsigned long long a0 = dup2(af[i].x), a1 = dup2(af[i].y);
                unsigned long long a2 = dup2(af[i].z), a3 = dup2(af[i].w);
                fma2(sc2[i][0], a0, bf[0][0]); fma2(sc2[i][1], a0, bf[0][1]);
                fma2(sc2[i][0], a1, bf[1][0]); fma2(sc2[i][1], a1, bf[1][1]);
                fma2(sc2[i][0], a2, bf[2][0]); fma2(sc2[i][1], a2, bf[2][1]);
                fma2(sc2[i][0], a3, bf[3][0]); fma2(sc2[i][1], a3, bf[3][1]);
            }
        }

        const bool diag = (kt == qtile);
        float pfrag[4][4];
#pragma unroll
        for (int i = 0; i < 4; i++) {
            float2 p01 = unpk(sc2[i][0]);
            float2 p23 = unpk(sc2[i][1]);
            float s0 = p01.x, s1 = p01.y, s2 = p23.x, s3 = p23.y;
            if (diag) {
                const int rg = qbase + (ty << 2) + i;
                const int cg = kbase + (tx << 2);
                if (cg + 0 > rg) s0 = NEG_INF;
                if (cg + 1 > rg) s1 = NEG_INF;
                if (cg + 2 > rg) s2 = NEG_INF;
                if (cg + 3 > rg) s3 = NEG_INF;
            }
            float rmax = fmaxf(fmaxf(s0, s1), fmaxf(s2, s3));
#pragma unroll
            for (int o = 8; o >= 1; o >>= 1)
                rmax = fmaxf(rmax, __shfl_xor_sync(0xffffffffu, rmax, o, 16));
            const float mnew = fmaxf(mrow[i], rmax);
            const float alpha = __expf(mrow[i] - mnew);
            const float p0 = __expf(s0 - mnew);
            const float p1 = __expf(s1 - mnew);
            const float p2 = __expf(s2 - mnew);
            const float p3 = __expf(s3 - mnew);
            float rsum = (p0 + p1) + (p2 + p3);
#pragma unroll
            for (int o = 8; o >= 1; o >>= 1)
                rsum += __shfl_xor_sync(0xffffffffu, rsum, o, 16);
            lrow[i] = lrow[i] * alpha + rsum;
            mrow[i] = mnew;
            unsigned long long al2 = dup2(alpha);
            mul2(oacc[i][0], al2);
            mul2(oacc[i][1], al2);
            pfrag[i][0] = p0; pfrag[i][1] = p1; pfrag[i][2] = p2; pfrag[i][3] = p3;
        }

        __syncthreads();
#pragma unroll
        for (int i = 0; i < 4; i++)
            *(float4*)&KPs[((ty << 2) + i) * 64 + (tx << 2)] = *(float4*)&pfrag[i][0];
        __syncthreads();

#pragma unroll
        for (int c0 = 0; c0 < 64; c0 += 4) {
            float4 pf[4];
#pragma unroll
            for (int i = 0; i < 4; i++)
                pf[i] = *(float4*)&KPs[((ty << 2) + i) * 64 + c0];
            unsigned long long vf[4][2];
#pragma unroll
            for (int k = 0; k < 4; k++) {
                ulonglong2 t = *(ulonglong2*)&Vs[(c0 + k) * 64 + (tx << 2)];
                vf[k][0] = t.x; vf[k][1] = t.y;
            }
#pragma unroll
            for (int i = 0; i < 4; i++) {
                unsigned long long p0 = dup2(pf[i].x), p1 = dup2(pf[i].y);
                unsigned long long p2 = dup2(pf[i].z), p3 = dup2(pf[i].w);
                fma2(oacc[i][0], p0, vf[0][0]); fma2(oacc[i][1], p0, vf[0][1]);
                fma2(oacc[i][0], p1, vf[1][0]); fma2(oacc[i][1], p1, vf[1][1]);
                fma2(oacc[i][0], p2, vf[2][0]); fma2(oacc[i][1], p2, vf[2][1]);
                fma2(oacc[i][0], p3, vf[3][0]); fma2(oacc[i][1], p3, vf[3][1]);
            }
        }
    }

    const int b = bh >> 4, h = bh & 15;
#pragma unroll
    for (int i = 0; i < 4; i++) {
        const int s = qbase + (ty << 2) + i;
        const float inv = 1.0f / lrow[i];
        float2 o01 = unpk(oacc[i][0]);
        float2 o23 = unpk(oacc[i][1]);
        float4 o4 = make_float4(o01.x * inv, o01.y * inv, o23.x * inv, o23.y * inv);
        *(float4*)(out + ((size_t)b * S_LEN + s) * E_DIM + h * HD + (tx << 2)) = o4;
    }
}

// ============================================================================
// Launch
// ============================================================================
extern "C" void kernel_launch(void* const* d_in, const int* in_sizes, int n_in,
                              void* d_out, int out_size) {
    (void)in_sizes; (void)n_in; (void)out_size;
    const float* x = (const float*)d_in[0];   // [4,2048,1024] fp32
    const float* w = (const float*)d_in[1];   // [1024,3072] fp32
    float* out = (float*)d_out;               // [4,2048,1024] fp32

    static int smem_set = 0;
    if (!smem_set) {
        cudaFuncSetAttribute(qkv_mma,
                             cudaFuncAttributeMaxDynamicSharedMemorySize, GSM);
        smem_set = 1;
    }

    split_x<<<(size_t)M_TOT * K_TOT / 4 / 256, 256>>>(x);   // 8192 blocks
    split_wt<<<N_TOT, 256>>>(w);                            // 3072 blocks
    qkv_mma<<<dim3(N_TOT / 128, M_TOT / 128), 256, GSM>>>();
    attn_kernel<<<dim3(S_LEN / 64, B_SZ * NH), 256>>>(out);
}

// round 14
// speedup vs baseline: 1.5998x; 1.0029x over previous
#include <cuda_runtime.h>
#include <cuda_bf16.h>
#include <cstdint>
#include <cstddef>

// Problem constants
#define B_SZ  4
#define S_LEN 2048
#define E_DIM 1024
#define NH    16
#define HD    64
#define M_TOT (B_SZ * S_LEN)   // 8192
#define N_TOT (3 * E_DIM)      // 3072
#define K_TOT E_DIM            // 1024

// ---------------------------------------------------------------------------
// Device-global scratch (no runtime allocation allowed)
// ---------------------------------------------------------------------------
__device__ float g_q[(size_t)B_SZ * NH * S_LEN * HD];
__device__ float g_k[(size_t)B_SZ * NH * S_LEN * HD];
__device__ float g_v[(size_t)B_SZ * NH * S_LEN * HD];

// bf16 hi/lo splits: x as [M,K], W^T as [N,K]
__device__ __nv_bfloat16 g_xhi[(size_t)M_TOT * K_TOT];
__device__ __nv_bfloat16 g_xlo[(size_t)M_TOT * K_TOT];
__device__ __nv_bfloat16 g_wthi[(size_t)N_TOT * K_TOT];
__device__ __nv_bfloat16 g_wtlo[(size_t)N_TOT * K_TOT];

// ---------------------------------------------------------------------------
// f32x2 helpers (attention kernel)
// ---------------------------------------------------------------------------
__device__ __forceinline__ unsigned long long dup2(float x) {
    unsigned long long r;
    unsigned u = __float_as_uint(x);
    asm("mov.b64 %0, {%1, %1};" : "=l"(r) : "r"(u));
    return r;
}
__device__ __forceinline__ void fma2(unsigned long long& acc,
                                     unsigned long long a, unsigned long long b) {
    asm("fma.rn.f32x2 %0, %1, %2, %0;" : "+l"(acc) : "l"(a), "l"(b));
}
__device__ __forceinline__ void mul2(unsigned long long& acc, unsigned long long a) {
    asm("mul.rn.f32x2 %0, %0, %1;" : "+l"(acc) : "l"(a));
}
__device__ __forceinline__ float2 unpk(unsigned long long v) {
    unsigned lo, hi;
    asm("mov.b64 {%0, %1}, %2;" : "=r"(lo), "=r"(hi) : "l"(v));
    return make_float2(__uint_as_float(lo), __uint_as_float(hi));
}

// ---------------------------------------------------------------------------
// mma.sync / ldmatrix / cp.async helpers (baseline PTX, valid on sm_103)
// ---------------------------------------------------------------------------
__device__ __forceinline__ uint32_t smem_u32(const void* p) {
    uint32_t a;
    asm("{ .reg .u64 t; cvta.to.shared.u64 t, %1; cvt.u32.u64 %0, t; }"
        : "=r"(a) : "l"(p));
    return a;
}
__device__ __forceinline__ void ldm_x4(uint32_t* r, uint32_t addr) {
    asm volatile("ldmatrix.sync.aligned.m8n8.x4.shared.b16 {%0,%1,%2,%3}, [%4];"
                 : "=r"(r[0]), "=r"(r[1]), "=r"(r[2]), "=r"(r[3]) : "r"(addr));
}
__device__ __forceinline__ void mma16816(float* c, const uint32_t* a,
                                         uint32_t b0, uint32_t b1) {
    asm volatile(
        "mma.sync.aligned.m16n8k16.row.col.f32.bf16.bf16.f32 "
        "{%0,%1,%2,%3}, {%4,%5,%6,%7}, {%8,%9}, {%0,%1,%2,%3};"
        : "+f"(c[0]), "+f"(c[1]), "+f"(c[2]), "+f"(c[3])
        : "r"(a[0]), "r"(a[1]), "r"(a[2]), "r"(a[3]), "r"(b0), "r"(b1));
}
__device__ __forceinline__ void cp_async16(uint32_t saddr, const void* gaddr) {
    asm volatile("cp.async.cg.shared.global [%0], [%1], 16;"
                 :: "r"(saddr), "l"(gaddr));
}
#define CP_COMMIT() asm volatile("cp.async.commit_group;" ::: "memory")
#define CP_WAIT2()  asm volatile("cp.async.wait_group 2;" ::: "memory")

// ---------------------------------------------------------------------------
// Split pre-pass kernels: fp32 -> bf16 hi/lo
// ---------------------------------------------------------------------------
__global__ __launch_bounds__(256) void split_x(const float* __restrict__ x) {
    size_t i = ((size_t)blockIdx.x * 256 + threadIdx.x) * 4;
    float4 v = *(const float4*)(x + i);
    __nv_bfloat16 h0 = __float2bfloat16(v.x), h1 = __float2bfloat16(v.y);
    __nv_bfloat16 h2 = __float2bfloat16(v.z), h3 = __float2bfloat16(v.w);
    __nv_bfloat16 l0 = __float2bfloat16(v.x - __bfloat162float(h0));
    __nv_bfloat16 l1 = __float2bfloat16(v.y - __bfloat162float(h1));
    __nv_bfloat16 l2 = __float2bfloat16(v.z - __bfloat162float(h2));
    __nv_bfloat16 l3 = __float2bfloat16(v.w - __bfloat162float(h3));
    *(ushort4*)(g_xhi + i) = make_ushort4(
        __bfloat16_as_ushort(h0), __bfloat16_as_ushort(h1),
        __bfloat16_as_ushort(h2), __bfloat16_as_ushort(h3));
    *(ushort4*)(g_xlo + i) = make_ushort4(
        __bfloat16_as_ushort(l0), __bfloat16_as_ushort(l1),
        __bfloat16_as_ushort(l2), __bfloat16_as_ushort(l3));
}

// transpose W [K,N] -> W^T [N,K] with split (L2 catches the line re-reads)
__global__ __launch_bounds__(256) void split_wt(const float* __restrict__ w) {
    const int n = blockIdx.x;              // 0..3071
    const int k0 = threadIdx.x * 4;        // 0..1020
    float v[4];
#pragma unroll
    for (int j = 0; j < 4; j++) v[j] = w[(size_t)(k0 + j) * N_TOT + n];
    unsigned short hh[4], ll[4];
#pragma unroll
    for (int j = 0; j < 4; j++) {
        __nv_bfloat16 h = __float2bfloat16(v[j]);
        __nv_bfloat16 l = __float2bfloat16(v[j] - __bfloat162float(h));
        hh[j] = __bfloat16_as_ushort(h);
        ll[j] = __bfloat16_as_ushort(l);
    }
    *(ushort4*)(g_wthi + (size_t)n * K_TOT + k0) = make_ushort4(hh[0], hh[1], hh[2], hh[3]);
    *(ushort4*)(g_wtlo + (size_t)n * K_TOT + k0) = make_ushort4(ll[0], ll[1], ll[2], ll[3]);
}

// ---------------------------------------------------------------------------
// QKV GEMM via mma.sync bf16 (error-compensated split):
//   D = Ah.Bh + Ah.Bl + Al.Bh,  fp32 accum.
// 128x128 CTA tile, BK=64 (128B rows, SW128 swizzle), 8 warps (4x2 grid,
// 32x64 warp tile), 3-stage cp.async pipeline.
// ---------------------------------------------------------------------------
#define BKC    64
#define NCHUNK (K_TOT / BKC)     // 16
#define OPBYTES (128 * 128)      // 16384: 128 rows x 128B
#define STB    (4 * OPBYTES)     // 65536 per stage (Ah, Al, Bh, Bl)
#define GSM    (3 * STB)         // 196608 dynamic smem

__global__ __launch_bounds__(256, 1) void qkv_mma() {
    extern __shared__ char sm[];
    const int tid = threadIdx.x;
    const int lane = tid & 31;
    const int w = tid >> 5;
    const int wr = w & 3, wc = w >> 2;       // 4x2 warp grid
    const int wm0 = wr * 32, wn0 = wc * 64;
    const int m0 = (int)blockIdx.y << 7;
    const int n0 = (int)blockIdx.x << 7;
    const uint32_t smb = smem_u32(sm);

    const __nv_bfloat16* srcs[4] = {
        g_xhi + (size_t)m0 * K_TOT, g_xlo + (size_t)m0 * K_TOT,
        g_wthi + (size_t)n0 * K_TOT, g_wtlo + (size_t)n0 * K_TOT };

    auto issue_stage = [&](int buf, int kc) {
        const int koff = kc * BKC;
#pragma unroll
        for (int op = 0; op < 4; op++) {
            const uint32_t sb = smb + buf * STB + op * OPBYTES;
            const __nv_bfloat16* gp = srcs[op] + koff;
#pragma unroll
            for (int t = 0; t < 4; t++) {
                const int idx = tid + t * 256;
                const int row = idx >> 3, seg = idx & 7;
                uint32_t off = (uint32_t)(row * 128 + seg * 16);
                off ^= (off >> 3) & 0x70;              // SW128 swizzle
                cp_async16(sb + off, gp + (size_t)row * K_TOT + seg * 8);
            }
        }
    };

    float acc[2][8][4];
#pragma unroll
    for (int i = 0; i < 2; i++)
#pragma unroll
        for (int j = 0; j < 8; j++)
#pragma unroll
            for (int q = 0; q < 4; q++) acc[i][j][q] = 0.0f;

    issue_stage(0, 0); CP_COMMIT();
    issue_stage(1, 1); CP_COMMIT();

    for (int c = 0; c < NCHUNK; c++) {
        if (c + 2 < NCHUNK) issue_stage((c + 2) % 3, c + 2);
        CP_COMMIT();                 // always commit (keeps group count uniform)
        CP_WAIT2();                  // stage c complete
        __syncthreads();

        const uint32_t ab = smb + (c % 3) * STB;
        const uint32_t alb = ab + OPBYTES;
        const uint32_t bhb = ab + 2 * OPBYTES;
        const uint32_t blb = ab + 3 * OPBYTES;

#pragma unroll
        for (int ks = 0; ks < 4; ks++) {
            uint32_t ah[2][4], al[2][4];
#pragma unroll
            for (int mi = 0; mi < 2; mi++) {
                const int row = wm0 + mi * 16 + (lane & 15);
                const int seg = ks * 2 + (lane >> 4);
                const uint32_t off = row * 128 + (((seg ^ (row & 7)) & 7) << 4);
                ldm_x4(ah[mi], ab + off);
                ldm_x4(al[mi], alb + off);
            }
            uint32_t bh[4][4], bl[4][4];
#pragma unroll
            for (int nf = 0; nf < 4; nf++) {
                const int row = wn0 + nf * 16 + (lane & 7) + ((lane >> 4) << 3);
                const int seg = ks * 2 + ((lane >> 3) & 1);
                const uint32_t off = row * 128 + (((seg ^ (row & 7)) & 7) << 4);
                ldm_x4(bh[nf], bhb + off);
                ldm_x4(bl[nf], blb + off);
            }
#pragma unroll
            for (int mi = 0; mi < 2; mi++)
#pragma unroll
                for (int nf = 0; nf < 4; nf++) {
                    mma16816(acc[mi][2 * nf],     ah[mi], bh[nf][0], bh[nf][1]);
                    mma16816(acc[mi][2 * nf + 1], ah[mi], bh[nf][2], bh[nf][3]);
                    mma16816(acc[mi][2 * nf],     ah[mi], bl[nf][0], bl[nf][1]);
                    mma16816(acc[mi][2 * nf + 1], ah[mi], bl[nf][2], bl[nf][3]);
                    mma16816(acc[mi][2 * nf],     al[mi], bh[nf][0], bh[nf][1]);
                    mma16816(acc[mi][2 * nf + 1], al[mi], bh[nf][2], bh[nf][3]);
                }
        }
        __syncthreads();   // all reads of buf done before it is refilled
    }

    // epilogue: scatter warp's 32x64 C tile into [B,H,S,D] Q/K/V
    const int qr = lane >> 2;
    const int qc = (lane & 3) << 1;
    const int bb = m0 >> 11;                 // whole tile in one batch
    const int ncol0 = n0 + wn0;              // 64-aligned -> one (which, head)
    const int which = ncol0 >> 10;
    const int h = (ncol0 >> 6) & (NH - 1);
    float* basep = (which == 0 ? g_q : which == 1 ? g_k : g_v)
                   + ((size_t)(bb * NH + h)) * S_LEN * HD;
    const float sc = (which == 0) ? 0.125f : 1.0f;   // fold 1/sqrt(D) into Q
    const int s00 = (m0 & (S_LEN - 1)) + wm0;

#pragma unroll
    for (int mi = 0; mi < 2; mi++)
#pragma unroll
        for (int nf8 = 0; nf8 < 8; nf8++) {
            const int d = nf8 * 8 + qc;
            const int s0 = s00 + mi * 16 + qr;
            float2 v0 = make_float2(acc[mi][nf8][0] * sc, acc[mi][nf8][1] * sc);
            float2 v1 = make_float2(acc[mi][nf8][2] * sc, acc[mi][nf8][3] * sc);
            *(float2*)(basep + (size_t)s0 * HD + d) = v0;
            *(float2*)(basep + (size_t)(s0 + 8) * HD + d) = v1;
        }
}

// ============================================================================
// Kernel 2: causal flash attention, fp32, f32x2 packed FMA (UNCHANGED)
// ============================================================================
__global__ __launch_bounds__(256, 2) void attn_kernel(float* __restrict__ out) {
    __shared__ float Qs[64 * 64];    // [r][d]
    __shared__ float KPs[64 * 64];   // K^T swizzled [d][c], then P [r][c]
    __shared__ float Vs[64 * 64];    // [c][d]

    const int tid = threadIdx.x;
    const int tx = tid & 15, ty = tid >> 4;
    const int qtile = (int)gridDim.x - 1 - (int)blockIdx.x;  // long blocks first
    const int bh = blockIdx.y;
    const int qbase = qtile << 6;
    const float NEG_INF = __int_as_float(0xff800000);

    const float* Qg = g_q + (size_t)bh * S_LEN * HD;
    const float* Kg = g_k + (size_t)bh * S_LEN * HD;
    const float* Vg = g_v + (size_t)bh * S_LEN * HD;

    const int lr = tid >> 2;   // 0..63 (row)
    const int lv = tid & 3;    // 0..3  (vec)

#pragma unroll
    for (int c = 0; c < 4; c++) {
        const int dv = lv + (c << 2);
        *(float4*)&Qs[lr * 64 + (dv << 2)] =
            *(const float4*)(Qg + (size_t)(qbase + lr) * HD + (dv << 2));
    }

    float mrow[4], lrow[4];
    unsigned long long oacc[4][2];
#pragma unroll
    for (int i = 0; i < 4; i++) {
        mrow[i] = NEG_INF; lrow[i] = 0.0f;
        oacc[i][0] = 0ULL; oacc[i][1] = 0ULL;
    }

    for (int kt = 0; kt <= qtile; kt++) {
        const int kbase = kt << 6;
        __syncthreads();

#pragma unroll
        for (int c = 0; c < 4; c++) {
            const int dv = lv + (c << 2);
            const int d0 = dv << 2;
            float4 kv = *(const float4*)(Kg + (size_t)(kbase + lr) * HD + d0);
            const int q = lr >> 2, lo = lr & 3;
            KPs[(d0 + 0) * 64 + ((q ^ ((d0 + 0) & 15)) << 2) + lo] = kv.x;
            KPs[(d0 + 1) * 64 + ((q ^ ((d0 + 1) & 15)) << 2) + lo] = kv.y;
            KPs[(d0 + 2) * 64 + ((q ^ ((d0 + 2) & 15)) << 2) + lo] = kv.z;
            KPs[(d0 + 3) * 64 + ((q ^ ((d0 + 3) & 15)) << 2) + lo] = kv.w;
            *(float4*)&Vs[lr * 64 + d0] =
                *(const float4*)(Vg + (size_t)(kbase + lr) * HD + d0);
        }
        __syncthreads();

        unsigned long long sc2[4][2];
#pragma unroll
        for (int i = 0; i < 4; i++) { sc2[i][0] = 0ULL; sc2[i][1] = 0ULL; }

#pragma unroll
        for (int d0 = 0; d0 < 64; d0 += 4) {
            float4 af[4];
#pragma unroll
            for (int i = 0; i < 4; i++)
                af[i] = *(float4*)&Qs[((ty << 2) + i) * 64 + d0];
            unsigned long long bf[4][2];
#pragma unroll
            for (int dd = 0; dd < 4; dd++) {
                const int d = d0 + dd;
                ulonglong2 t = *(ulonglong2*)&KPs[d * 64 + ((tx ^ (d & 15)) << 2)];
                bf[dd][0] = t.x; bf[dd][1] = t.y;
            }
#pragma unroll
            for (int i = 0; i < 4; i++) {
                unsigned long long a0 = dup2(af[i].x), a1 = dup2(af[i].y);
                unsigned long long a2 = dup2(af[i].z), a3 = dup2(af[i].w);
                fma2(sc2[i][0], a0, bf[0][0]); fma2(sc2[i][1], a0, bf[0][1]);
                fma2(sc2[i][0], a1, bf[1][0]); fma2(sc2[i][1], a1, bf[1][1]);
                fma2(sc2[i][0], a2, bf[2][0]); fma2(sc2[i][1], a2, bf[2][1]);
                fma2(sc2[i][0], a3, bf[3][0]); fma2(sc2[i][1], a3, bf[3][1]);
            }
        }

        const bool diag = (kt == qtile);
        float pfrag[4][4];
#pragma unroll
        for (int i = 0; i < 4; i++) {
            float2 p01 = unpk(sc2[i][0]);
            float2 p23 = unpk(sc2[i][1]);
            float s0 = p01.x, s1 = p01.y, s2 = p23.x, s3 = p23.y;
            if (diag) {
                const int rg = qbase + (ty << 2) + i;
                const int cg = kbase + (tx << 2);
                if (cg + 0 > rg) s0 = NEG_INF;
                if (cg + 1 > rg) s1 = NEG_INF;
                if (cg + 2 > rg) s2 = NEG_INF;
                if (cg + 3 > rg) s3 = NEG_INF;
            }
            float rmax = fmaxf(fmaxf(s0, s1), fmaxf(s2, s3));
#pragma unroll
            for (int o = 8; o >= 1; o >>= 1)
                rmax = fmaxf(rmax, __shfl_xor_sync(0xffffffffu, rmax, o, 16));
            const float mnew = fmaxf(mrow[i], rmax);
            const float alpha = __expf(mrow[i] - mnew);
            const float p0 = __expf(s0 - mnew);
            const float p1 = __expf(s1 - mnew);
            const float p2 = __expf(s2 - mnew);
            const float p3 = __expf(s3 - mnew);
            float rsum = (p0 + p1) + (p2 + p3);
#pragma unroll
            for (int o = 8; o >= 1; o >>= 1)
                rsum += __shfl_xor_sync(0xffffffffu, rsum, o, 16);
            lrow[i] = lrow[i] * alpha + rsum;
            mrow[i] = mnew;
            unsigned long long al2 = dup2(alpha);
            mul2(oacc[i][0], al2);
            mul2(oacc[i][1], al2);
            pfrag[i][0] = p0; pfrag[i][1] = p1; pfrag[i][2] = p2; pfrag[i][3] = p3;
        }

        __syncthreads();
#pragma unroll
        for (int i = 0; i < 4; i++)
            *(float4*)&KPs[((ty << 2) + i) * 64 + (tx << 2)] = *(float4*)&pfrag[i][0];
        __syncthreads();

#pragma unroll
        for (int c0 = 0; c0 < 64; c0 += 4) {
            float4 pf[4];
#pragma unroll
            for (int i = 0; i < 4; i++)
                pf[i] = *(float4*)&KPs[((ty << 2) + i) * 64 + c0];
            unsigned long long vf[4][2];
#pragma unroll
            for (int k = 0; k < 4; k++) {
                ulonglong2 t = *(ulonglong2*)&Vs[(c0 + k) * 64 + (tx << 2)];
                vf[k][0] = t.x; vf[k][1] = t.y;
            }
#pragma unroll
            for (int i = 0; i < 4; i++) {
                unsigned long long p0 = dup2(pf[i].x), p1 = dup2(pf[i].y);
                unsigned long long p2 = dup2(pf[i].z), p3 = dup2(pf[i].w);
                fma2(oacc[i][0], p0, vf[0][0]); fma2(oacc[i][1], p0, vf[0][1]);
                fma2(oacc[i][0], p1, vf[1][0]); fma2(oacc[i][1], p1, vf[1][1]);
                fma2(oacc[i][0], p2, vf[2][0]); fma2(oacc[i][1], p2, vf[2][1]);
                fma2(oacc[i][0], p3, vf[3][0]); fma2(oacc[i][1], p3, vf[3][1]);
            }
        }
    }

    const int b = bh >> 4, h = bh & 15;
#pragma unroll
    for (int i = 0; i < 4; i++) {
        const int s = qbase + (ty << 2) + i;
        const float inv = 1.0f / lrow[i];
        float2 o01 = unpk(oacc[i][0]);
        float2 o23 = unpk(oacc[i][1]);
        float4 o4 = make_float4(o01.x * inv, o01.y * inv, o23.x * inv, o23.y * inv);
        *(float4*)(out + ((size_t)b * S_LEN + s) * E_DIM + h * HD + (tx << 2)) = o4;
    }
}

// ============================================================================
// Launch
// ============================================================================
extern "C" void kernel_launch(void* const* d_in, const int* in_sizes, int n_in,
                              void* d_out, int out_size) {
    (void)in_sizes; (void)n_in; (void)out_size;
    const float* x = (const float*)d_in[0];   // [4,2048,1024] fp32
    const float* w = (const float*)d_in[1];   // [1024,3072] fp32
    float* out = (float*)d_out;               // [4,2048,1024] fp32

    static int smem_set = 0;
    if (!smem_set) {
        cudaFuncSetAttribute(qkv_mma,
                             cudaFuncAttributeMaxDynamicSharedMemorySize, GSM);
        smem_set = 1;
    }

    split_x<<<(size_t)M_TOT * K_TOT / 4 / 256, 256>>>(x);   // 8192 blocks
    split_wt<<<N_TOT, 256>>>(w);                            // 3072 blocks
    qkv_mma<<<dim3(N_TOT / 128, M_TOT / 128), 256, GSM>>>();
    attn_kernel<<<dim3(S_LEN / 64, B_SZ * NH), 256>>>(out);
}

// round 15
// speedup vs baseline: 3.0125x; 1.8831x over previous
#include <cuda_runtime.h>
#include <cuda_bf16.h>
#include <cstdint>
#include <cstddef>

// Problem constants
#define B_SZ  4
#define S_LEN 2048
#define E_DIM 1024
#define NH    16
#define HD    64
#define M_TOT (B_SZ * S_LEN)   // 8192
#define N_TOT (3 * E_DIM)      // 3072
#define K_TOT E_DIM            // 1024

#define LOG2E 1.4426950408889634f

// ---------------------------------------------------------------------------
// Device-global scratch (no runtime allocation allowed)
// Q/K/V stored as bf16 hi/lo split pairs, [B,H,S,D] layout.
// ---------------------------------------------------------------------------
__device__ __nv_bfloat16 g_qhi[(size_t)B_SZ * NH * S_LEN * HD];
__device__ __nv_bfloat16 g_qlo[(size_t)B_SZ * NH * S_LEN * HD];
__device__ __nv_bfloat16 g_khi[(size_t)B_SZ * NH * S_LEN * HD];
__device__ __nv_bfloat16 g_klo[(size_t)B_SZ * NH * S_LEN * HD];
__device__ __nv_bfloat16 g_vhi[(size_t)B_SZ * NH * S_LEN * HD];
__device__ __nv_bfloat16 g_vlo[(size_t)B_SZ * NH * S_LEN * HD];

// bf16 hi/lo splits of GEMM inputs: x as [M,K], W^T as [N,K]
__device__ __nv_bfloat16 g_xhi[(size_t)M_TOT * K_TOT];
__device__ __nv_bfloat16 g_xlo[(size_t)M_TOT * K_TOT];
__device__ __nv_bfloat16 g_wthi[(size_t)N_TOT * K_TOT];
__device__ __nv_bfloat16 g_wtlo[(size_t)N_TOT * K_TOT];

// ---------------------------------------------------------------------------
// mma.sync / ldmatrix / cp.async helpers (baseline PTX, valid on sm_103)
// ---------------------------------------------------------------------------
__device__ __forceinline__ uint32_t smem_u32(const void* p) {
    uint32_t a;
    asm("{ .reg .u64 t; cvta.to.shared.u64 t, %1; cvt.u32.u64 %0, t; }"
        : "=r"(a) : "l"(p));
    return a;
}
__device__ __forceinline__ void ldm_x4(uint32_t* r, uint32_t addr) {
    asm volatile("ldmatrix.sync.aligned.m8n8.x4.shared.b16 {%0,%1,%2,%3}, [%4];"
                 : "=r"(r[0]), "=r"(r[1]), "=r"(r[2]), "=r"(r[3]) : "r"(addr));
}
__device__ __forceinline__ void ldm_x4_t(uint32_t* r, uint32_t addr) {
    asm volatile("ldmatrix.sync.aligned.m8n8.x4.trans.shared.b16 {%0,%1,%2,%3}, [%4];"
                 : "=r"(r[0]), "=r"(r[1]), "=r"(r[2]), "=r"(r[3]) : "r"(addr));
}
__device__ __forceinline__ void mma16816(float* c, const uint32_t* a,
                                         uint32_t b0, uint32_t b1) {
    asm volatile(
        "mma.sync.aligned.m16n8k16.row.col.f32.bf16.bf16.f32 "
        "{%0,%1,%2,%3}, {%4,%5,%6,%7}, {%8,%9}, {%0,%1,%2,%3};"
        : "+f"(c[0]), "+f"(c[1]), "+f"(c[2]), "+f"(c[3])
        : "r"(a[0]), "r"(a[1]), "r"(a[2]), "r"(a[3]), "r"(b0), "r"(b1));
}
__device__ __forceinline__ void cp_async16(uint32_t saddr, const void* gaddr) {
    asm volatile("cp.async.cg.shared.global [%0], [%1], 16;"
                 :: "r"(saddr), "l"(gaddr));
}
#define CP_COMMIT() asm volatile("cp.async.commit_group;" ::: "memory")
#define CP_WAIT2()  asm volatile("cp.async.wait_group 2;" ::: "memory")

// FMA-pipe exp: 2^y with y = x*log2e, y <= 0 (avoids the MUFU bottleneck)
__device__ __forceinline__ float exp2p(float y) {
    y = fmaxf(y, -126.0f);                       // -inf masks -> ~0
    float t = y + 12582912.0f;                   // 1.5*2^23: round-to-int
    int n = __float_as_int(t) - 0x4B400000;
    float f = y - (t - 12582912.0f);             // f in [-0.5, 0.5]
    float p = 0.0013333558f;
    p = fmaf(p, f, 0.0096181291f);
    p = fmaf(p, f, 0.0555041087f);
    p = fmaf(p, f, 0.2402265070f);
    p = fmaf(p, f, 0.6931471806f);
    p = fmaf(p, f, 1.0f);
    return __int_as_float(__float_as_int(p) + (n << 23));
}

// ---------------------------------------------------------------------------
// Split pre-pass kernels: fp32 -> bf16 hi/lo
// ---------------------------------------------------------------------------
__global__ __launch_bounds__(256) void split_x(const float* __restrict__ x) {
    size_t i = ((size_t)blockIdx.x * 256 + threadIdx.x) * 4;
    float4 v = *(const float4*)(x + i);
    __nv_bfloat16 h0 = __float2bfloat16(v.x), h1 = __float2bfloat16(v.y);
    __nv_bfloat16 h2 = __float2bfloat16(v.z), h3 = __float2bfloat16(v.w);
    __nv_bfloat16 l0 = __float2bfloat16(v.x - __bfloat162float(h0));
    __nv_bfloat16 l1 = __float2bfloat16(v.y - __bfloat162float(h1));
    __nv_bfloat16 l2 = __float2bfloat16(v.z - __bfloat162float(h2));
    __nv_bfloat16 l3 = __float2bfloat16(v.w - __bfloat162float(h3));
    *(ushort4*)(g_xhi + i) = make_ushort4(
        __bfloat16_as_ushort(h0), __bfloat16_as_ushort(h1),
        __bfloat16_as_ushort(h2), __bfloat16_as_ushort(h3));
    *(ushort4*)(g_xlo + i) = make_ushort4(
        __bfloat16_as_ushort(l0), __bfloat16_as_ushort(l1),
        __bfloat16_as_ushort(l2), __bfloat16_as_ushort(l3));
}

__global__ __launch_bounds__(256) void split_wt(const float* __restrict__ w) {
    const int n = blockIdx.x;
    const int k0 = threadIdx.x * 4;
    float v[4];
#pragma unroll
    for (int j = 0; j < 4; j++) v[j] = w[(size_t)(k0 + j) * N_TOT + n];
    unsigned short hh[4], ll[4];
#pragma unroll
    for (int j = 0; j < 4; j++) {
        __nv_bfloat16 h = __float2bfloat16(v[j]);
        __nv_bfloat16 l = __float2bfloat16(v[j] - __bfloat162float(h));
        hh[j] = __bfloat16_as_ushort(h);
        ll[j] = __bfloat16_as_ushort(l);
    }
    *(ushort4*)(g_wthi + (size_t)n * K_TOT + k0) = make_ushort4(hh[0], hh[1], hh[2], hh[3]);
    *(ushort4*)(g_wtlo + (size_t)n * K_TOT + k0) = make_ushort4(ll[0], ll[1], ll[2], ll[3]);
}

// ---------------------------------------------------------------------------
// QKV GEMM via mma.sync bf16 split (D = Ah.Bh + Ah.Bl + Al.Bh, fp32 accum).
// Epilogue writes Q/K/V directly as bf16 hi/lo pairs in [B,H,S,D].
// ---------------------------------------------------------------------------
#define BKC    64
#define NCHUNK (K_TOT / BKC)     // 16
#define OPBYTES (128 * 128)
#define STB    (4 * OPBYTES)
#define GSM    (3 * STB)         // 196608

__global__ __launch_bounds__(256, 1) void qkv_mma() {
    extern __shared__ char sm[];
    const int tid = threadIdx.x;
    const int lane = tid & 31;
    const int w = tid >> 5;
    const int wr = w & 3, wc = w >> 2;
    const int wm0 = wr * 32, wn0 = wc * 64;
    const int m0 = (int)blockIdx.y << 7;
    const int n0 = (int)blockIdx.x << 7;
    const uint32_t smb = smem_u32(sm);

    const __nv_bfloat16* srcs[4] = {
        g_xhi + (size_t)m0 * K_TOT, g_xlo + (size_t)m0 * K_TOT,
        g_wthi + (size_t)n0 * K_TOT, g_wtlo + (size_t)n0 * K_TOT };

    auto issue_stage = [&](int buf, int kc) {
        const int koff = kc * BKC;
#pragma unroll
        for (int op = 0; op < 4; op++) {
            const uint32_t sb = smb + buf * STB + op * OPBYTES;
            const __nv_bfloat16* gp = srcs[op] + koff;
#pragma unroll
            for (int t = 0; t < 4; t++) {
                const int idx = tid + t * 256;
                const int row = idx >> 3, seg = idx & 7;
                uint32_t off = (uint32_t)(row * 128 + seg * 16);
                off ^= (off >> 3) & 0x70;
                cp_async16(sb + off, gp + (size_t)row * K_TOT + seg * 8);
            }
        }
    };

    float acc[2][8][4];
#pragma unroll
    for (int i = 0; i < 2; i++)
#pragma unroll
        for (int j = 0; j < 8; j++)
#pragma unroll
            for (int q = 0; q < 4; q++) acc[i][j][q] = 0.0f;

    issue_stage(0, 0); CP_COMMIT();
    issue_stage(1, 1); CP_COMMIT();

    for (int c = 0; c < NCHUNK; c++) {
        if (c + 2 < NCHUNK) issue_stage((c + 2) % 3, c + 2);
        CP_COMMIT();
        CP_WAIT2();
        __syncthreads();

        const uint32_t ab = smb + (c % 3) * STB;
        const uint32_t alb = ab + OPBYTES;
        const uint32_t bhb = ab + 2 * OPBYTES;
        const uint32_t blb = ab + 3 * OPBYTES;

#pragma unroll
        for (int ks = 0; ks < 4; ks++) {
            uint32_t ah[2][4], al[2][4];
#pragma unroll
            for (int mi = 0; mi < 2; mi++) {
                const int row = wm0 + mi * 16 + (lane & 15);
                const int seg = ks * 2 + (lane >> 4);
                const uint32_t off = row * 128 + (((seg ^ (row & 7)) & 7) << 4);
                ldm_x4(ah[mi], ab + off);
                ldm_x4(al[mi], alb + off);
            }
            uint32_t bh[4][4], bl[4][4];
#pragma unroll
            for (int nf = 0; nf < 4; nf++) {
                const int row = wn0 + nf * 16 + (lane & 7) + ((lane >> 4) << 3);
                const int seg = ks * 2 + ((lane >> 3) & 1);
                const uint32_t off = row * 128 + (((seg ^ (row & 7)) & 7) << 4);
                ldm_x4(bh[nf], bhb + off);
                ldm_x4(bl[nf], blb + off);
            }
#pragma unroll
            for (int mi = 0; mi < 2; mi++)
#pragma unroll
                for (int nf = 0; nf < 4; nf++) {
                    mma16816(acc[mi][2 * nf],     ah[mi], bh[nf][0], bh[nf][1]);
                    mma16816(acc[mi][2 * nf + 1], ah[mi], bh[nf][2], bh[nf][3]);
                    mma16816(acc[mi][2 * nf],     ah[mi], bl[nf][0], bl[nf][1]);
                    mma16816(acc[mi][2 * nf + 1], ah[mi], bl[nf][2], bl[nf][3]);
                    mma16816(acc[mi][2 * nf],     al[mi], bh[nf][0], bh[nf][1]);
                    mma16816(acc[mi][2 * nf + 1], al[mi], bh[nf][2], bh[nf][3]);
                }
        }
        __syncthreads();
    }

    // epilogue: split each fp32 result to bf16 hi/lo, scatter to [B,H,S,D]
    const int qr = lane >> 2;
    const int qc = (lane & 3) << 1;
    const int bb = m0 >> 11;
    const int ncol0 = n0 + wn0;
    const int which = ncol0 >> 10;
    const int h = (ncol0 >> 6) & (NH - 1);
    const size_t hoff = ((size_t)(bb * NH + h)) * S_LEN * HD;
    __nv_bfloat16* hbase = (which == 0 ? g_qhi : which == 1 ? g_khi : g_vhi) + hoff;
    __nv_bfloat16* lbase = (which == 0 ? g_qlo : which == 1 ? g_klo : g_vlo) + hoff;
    const float sc = (which == 0) ? 0.125f : 1.0f;   // fold 1/sqrt(D) into Q
    const int s00 = (m0 & (S_LEN - 1)) + wm0;

#pragma unroll
    for (int mi = 0; mi < 2; mi++)
#pragma unroll
        for (int nf8 = 0; nf8 < 8; nf8++) {
            const int d = nf8 * 8 + qc;
            const int s0 = s00 + mi * 16 + qr;
#pragma unroll
            for (int rr = 0; rr < 2; rr++) {
                const float v0 = acc[mi][nf8][2 * rr + 0] * sc;
                const float v1 = acc[mi][nf8][2 * rr + 1] * sc;
                __nv_bfloat162 h2 = __floats2bfloat162_rn(v0, v1);
                float2 hf = __bfloat1622float2(h2);
                __nv_bfloat162 l2 = __floats2bfloat162_rn(v0 - hf.x, v1 - hf.y);
                const size_t idx = (size_t)(s0 + 8 * rr) * HD + d;
                *(__nv_bfloat162*)(hbase + idx) = h2;
                *(__nv_bfloat162*)(lbase + idx) = l2;
            }
        }
}

// ---------------------------------------------------------------------------
// Flash attention on mma.sync bf16 split + FMA-pipe softmax.
// CTA = 128 Q rows x 64 KV tile, 8 warps (16 Q rows each), 3-stage cp.async.
// smem: Qhi 16K | Qlo 16K | 3 x (Khi 8K | Klo 8K | Vhi 8K | Vlo 8K)
// ---------------------------------------------------------------------------
#define AT_STG 32768
#define AT_SMEM (32768 + 3 * AT_STG)   // 131072

__global__ __launch_bounds__(256, 1) void attn_mma(float* __restrict__ out) {
    extern __shared__ char smx[];
    const int tid = threadIdx.x, lane = tid & 31, w = tid >> 5;
    const int qt = (int)gridDim.x - 1 - (int)blockIdx.x;  // long CTAs first
    const int bh = blockIdx.y;
    const int qbase = qt << 7;
    const int nk = 2 * qt + 2;
    const uint32_t smb = smem_u32(smx);
    const uint32_t QH = smb, QL = smb + 16384;
    const uint32_t ST0 = smb + 32768;
    const float NEG_INF = __int_as_float(0xff800000);

    const size_t hoff = (size_t)bh * S_LEN * HD;
    const __nv_bfloat16* qhg = g_qhi + hoff + (size_t)qbase * HD;
    const __nv_bfloat16* qlg = g_qlo + hoff + (size_t)qbase * HD;
    const __nv_bfloat16* khg = g_khi + hoff;
    const __nv_bfloat16* klg = g_klo + hoff;
    const __nv_bfloat16* vhg = g_vhi + hoff;
    const __nv_bfloat16* vlg = g_vlo + hoff;

    // ---- Q load (once): 2 arrays x 128 rows x 8 segs ----
#pragma unroll
    for (int t = 0; t < 4; t++) {
        const int idx = tid + t * 256;
        const int row = idx >> 3, seg = idx & 7;
        const uint32_t off = row * 128 + (((seg ^ (row & 7)) & 7) << 4);
        cp_async16(QH + off, qhg + (size_t)row * HD + seg * 8);
        cp_async16(QL + off, qlg + (size_t)row * HD + seg * 8);
    }

    auto issue_kv = [&](int buf, int kc) {
        const size_t koff = (size_t)kc * 64 * HD;
        const __nv_bfloat16* gps[4] = { khg + koff, klg + koff,
                                        vhg + koff, vlg + koff };
#pragma unroll
        for (int op = 0; op < 4; op++) {
            const uint32_t sb = ST0 + buf * AT_STG + op * 8192;
#pragma unroll
            for (int t = 0; t < 2; t++) {
                const int idx = tid + t * 256;
                const int row = idx >> 3, seg = idx & 7;
                const uint32_t off = row * 128 + (((seg ^ (row & 7)) & 7) << 4);
                cp_async16(sb + off, gps[op] + (size_t)row * HD + seg * 8);
            }
        }
    };

    issue_kv(0, 0); CP_COMMIT();            // group 0: Q + stage 0
    if (nk > 1) issue_kv(1, 1);
    CP_COMMIT();                             // group 1: stage 1

    // persistent state (per lane: 2 row-groups r and r+8)
    float o[8][4];
#pragma unroll
    for (int i = 0; i < 8; i++)
#pragma unroll
        for (int j = 0; j < 4; j++) o[i][j] = 0.0f;
    float m0 = NEG_INF, m1 = NEG_INF, l0 = 0.0f, l1 = 0.0f;

    const int wq0 = qbase + w * 16;          // warp's first Q row (global)
    const int r0g = wq0 + (lane >> 2);
    const int r1g = r0g + 8;

    for (int c = 0; c < nk; c++) {
        if (c + 2 < nk) issue_kv((c + 2) % 3, c + 2);
        CP_COMMIT();
        CP_WAIT2();
        __syncthreads();

        const int kbase = c * 64;
        const bool active = (kbase <= wq0 + 15);

        if (active) {
            const uint32_t KHB = ST0 + (c % 3) * AT_STG;
            const uint32_t KLB = KHB + 8192;
            const uint32_t VHB = KHB + 16384;
            const uint32_t VLB = KHB + 24576;

            // ---- S = Q K^T (split, 3 terms) ----
            float s[8][4];
#pragma unroll
            for (int i = 0; i < 8; i++)
#pragma unroll
                for (int j = 0; j < 4; j++) s[i][j] = 0.0f;

#pragma unroll
            for (int ks = 0; ks < 4; ks++) {
                uint32_t qh[4], ql[4];
                {
                    const int row = w * 16 + (lane & 15);
                    const int seg = ks * 2 + (lane >> 4);
                    const uint32_t off = row * 128 + (((seg ^ (row & 7)) & 7) << 4);
                    ldm_x4(qh, QH + off);
                    ldm_x4(ql, QL + off);
                }
#pragma unroll
                for (int ng = 0; ng < 4; ng++) {
                    uint32_t kh[4], kl[4];
                    const int row = ng * 16 + (lane & 7) + ((lane >> 4) << 3);
                    const int seg = ks * 2 + ((lane >> 3) & 1);
                    const uint32_t off = row * 128 + (((seg ^ (row & 7)) & 7) << 4);
                    ldm_x4(kh, KHB + off);
                    ldm_x4(kl, KLB + off);
                    mma16816(s[2 * ng],     qh, kh[0], kh[1]);
                    mma16816(s[2 * ng + 1], qh, kh[2], kh[3]);
                    mma16816(s[2 * ng],     qh, kl[0], kl[1]);
                    mma16816(s[2 * ng + 1], qh, kl[2], kl[3]);
                    mma16816(s[2 * ng],     ql, kh[0], kh[1]);
                    mma16816(s[2 * ng + 1], ql, kh[2], kh[3]);
                }
            }

            // ---- causal mask ----
            if (kbase + 63 > wq0) {
#pragma unroll
                for (int nf = 0; nf < 8; nf++) {
                    const int cg = kbase + nf * 8 + ((lane & 3) << 1);
                    if (cg > r0g)     s[nf][0] = NEG_INF;
                    if (cg + 1 > r0g) s[nf][1] = NEG_INF;
                    if (cg > r1g)     s[nf][2] = NEG_INF;
                    if (cg + 1 > r1g) s[nf][3] = NEG_INF;
                }
            }

            // ---- online softmax (poly exp on FMA pipe) ----
            float mx0 = NEG_INF, mx1 = NEG_INF;
#pragma unroll
            for (int nf = 0; nf < 8; nf++) {
                mx0 = fmaxf(mx0, fmaxf(s[nf][0], s[nf][1]));
                mx1 = fmaxf(mx1, fmaxf(s[nf][2], s[nf][3]));
            }
            mx0 = fmaxf(mx0, __shfl_xor_sync(0xffffffffu, mx0, 1));
            mx0 = fmaxf(mx0, __shfl_xor_sync(0xffffffffu, mx0, 2));
            mx1 = fmaxf(mx1, __shfl_xor_sync(0xffffffffu, mx1, 1));
            mx1 = fmaxf(mx1, __shfl_xor_sync(0xffffffffu, mx1, 2));
            const float mn0 = fmaxf(m0, mx0), mn1 = fmaxf(m1, mx1);
            const float mn0L = mn0 * LOG2E, mn1L = mn1 * LOG2E;
            const float a0 = exp2p(fmaf(m0, LOG2E, -mn0L));
            const float a1 = exp2p(fmaf(m1, LOG2E, -mn1L));
            m0 = mn0; m1 = mn1;

            uint32_t ph2[8][2], pl2[8][2];
            float ps0 = 0.0f, ps1 = 0.0f;
#pragma unroll
            for (int nf = 0; nf < 8; nf++) {
                const float p0 = exp2p(fmaf(s[nf][0], LOG2E, -mn0L));
                const float p1 = exp2p(fmaf(s[nf][1], LOG2E, -mn0L));
                const float p2 = exp2p(fmaf(s[nf][2], LOG2E, -mn1L));
                const float p3 = exp2p(fmaf(s[nf][3], LOG2E, -mn1L));
                ps0 += p0 + p1; ps1 += p2 + p3;
                __nv_bfloat162 h01 = __floats2bfloat162_rn(p0, p1);
                __nv_bfloat162 h23 = __floats2bfloat162_rn(p2, p3);
                float2 f01 = __bfloat1622float2(h01);
                float2 f23 = __bfloat1622float2(h23);
                __nv_bfloat162 l01 = __floats2bfloat162_rn(p0 - f01.x, p1 - f01.y);
                __nv_bfloat162 l23 = __floats2bfloat162_rn(p2 - f23.x, p3 - f23.y);
                ph2[nf][0] = *(uint32_t*)&h01; ph2[nf][1] = *(uint32_t*)&h23;
                pl2[nf][0] = *(uint32_t*)&l01; pl2[nf][1] = *(uint32_t*)&l23;
            }
            ps0 += __shfl_xor_sync(0xffffffffu, ps0, 1);
            ps0 += __shfl_xor_sync(0xffffffffu, ps0, 2);
            ps1 += __shfl_xor_sync(0xffffffffu, ps1, 1);
            ps1 += __shfl_xor_sync(0xffffffffu, ps1, 2);
            l0 = fmaf(l0, a0, ps0);
            l1 = fmaf(l1, a1, ps1);
#pragma unroll
            for (int nf = 0; nf < 8; nf++) {
                o[nf][0] *= a0; o[nf][1] *= a0;
                o[nf][2] *= a1; o[nf][3] *= a1;
            }

            // ---- O += P V (split, 3 terms) ----
#pragma unroll
            for (int ks = 0; ks < 4; ks++) {
                uint32_t ah[4] = { ph2[2 * ks][0], ph2[2 * ks][1],
                                   ph2[2 * ks + 1][0], ph2[2 * ks + 1][1] };
                uint32_t al[4] = { pl2[2 * ks][0], pl2[2 * ks][1],
                                   pl2[2 * ks + 1][0], pl2[2 * ks + 1][1] };
#pragma unroll
                for (int ng = 0; ng < 4; ng++) {
                    uint32_t vh[4], vl[4];
                    const int row = ks * 16 + (lane & 15);
                    const int seg = ng * 2 + (lane >> 4);
                    const uint32_t off = row * 128 + (((seg ^ (row & 7)) & 7) << 4);
                    ldm_x4_t(vh, VHB + off);
                    ldm_x4_t(vl, VLB + off);
                    mma16816(o[2 * ng],     ah, vh[0], vh[1]);
                    mma16816(o[2 * ng + 1], ah, vh[2], vh[3]);
                    mma16816(o[2 * ng],     ah, vl[0], vl[1]);
                    mma16816(o[2 * ng + 1], ah, vl[2], vl[3]);
                    mma16816(o[2 * ng],     al, vh[0], vh[1]);
                    mma16816(o[2 * ng + 1], al, vh[2], vh[3]);
                }
            }
        }
        __syncthreads();
    }

    // ---- final write: out[b, s, h*64 + d] ----
    const int b = bh >> 4, h = bh & 15;
    const float inv0 = 1.0f / l0, inv1 = 1.0f / l1;
#pragma unroll
    for (int nf = 0; nf < 8; nf++) {
        const int d = h * HD + nf * 8 + ((lane & 3) << 1);
        float2 u0 = make_float2(o[nf][0] * inv0, o[nf][1] * inv0);
        float2 u1 = make_float2(o[nf][2] * inv1, o[nf][3] * inv1);
        *(float2*)(out + ((size_t)b * S_LEN + r0g) * E_DIM + d) = u0;
        *(float2*)(out + ((size_t)b * S_LEN + r1g) * E_DIM + d) = u1;
    }
}

// ============================================================================
// Launch
// ============================================================================
extern "C" void kernel_launch(void* const* d_in, const int* in_sizes, int n_in,
                              void* d_out, int out_size) {
    (void)in_sizes; (void)n_in; (void)out_size;
    const float* x = (const float*)d_in[0];   // [4,2048,1024] fp32
    const float* w = (const float*)d_in[1];   // [1024,3072] fp32
    float* out = (float*)d_out;               // [4,2048,1024] fp32

    static int smem_set = 0;
    if (!smem_set) {
        cudaFuncSetAttribute(qkv_mma,
                             cudaFuncAttributeMaxDynamicSharedMemorySize, GSM);
        cudaFuncSetAttribute(attn_mma,
                             cudaFuncAttributeMaxDynamicSharedMemorySize, AT_SMEM);
        smem_set = 1;
    }

    split_x<<<(size_t)M_TOT * K_TOT / 4 / 256, 256>>>(x);
    split_wt<<<N_TOT, 256>>>(w);
    qkv_mma<<<dim3(N_TOT / 128, M_TOT / 128), 256, GSM>>>();
    attn_mma<<<dim3(S_LEN / 128, B_SZ * NH), 256, AT_SMEM>>>(out);
}

// round 16
// speedup vs baseline: 3.0160x; 1.0011x over previous
#include <cuda_runtime.h>
#include <cuda_bf16.h>
#include <cstdint>
#include <cstddef>

// Problem constants
#define B_SZ  4
#define S_LEN 2048
#define E_DIM 1024
#define NH    16
#define HD    64
#define M_TOT (B_SZ * S_LEN)   // 8192
#define N_TOT (3 * E_DIM)      // 3072
#define K_TOT E_DIM            // 1024

#define LOG2E 1.4426950408889634f

// ---------------------------------------------------------------------------
// Device-global scratch (no runtime allocation allowed)
// Q/K/V stored as bf16 hi/lo split pairs, [B,H,S,D] layout.
// ---------------------------------------------------------------------------
__device__ __nv_bfloat16 g_qhi[(size_t)B_SZ * NH * S_LEN * HD];
__device__ __nv_bfloat16 g_qlo[(size_t)B_SZ * NH * S_LEN * HD];
__device__ __nv_bfloat16 g_khi[(size_t)B_SZ * NH * S_LEN * HD];
__device__ __nv_bfloat16 g_klo[(size_t)B_SZ * NH * S_LEN * HD];
__device__ __nv_bfloat16 g_vhi[(size_t)B_SZ * NH * S_LEN * HD];
__device__ __nv_bfloat16 g_vlo[(size_t)B_SZ * NH * S_LEN * HD];

// bf16 hi/lo splits of GEMM inputs: x as [M,K], W^T as [N,K]
__device__ __nv_bfloat16 g_xhi[(size_t)M_TOT * K_TOT];
__device__ __nv_bfloat16 g_xlo[(size_t)M_TOT * K_TOT];
__device__ __nv_bfloat16 g_wthi[(size_t)N_TOT * K_TOT];
__device__ __nv_bfloat16 g_wtlo[(size_t)N_TOT * K_TOT];

// ---------------------------------------------------------------------------
// mma.sync / ldmatrix / cp.async helpers (baseline PTX, valid on sm_103)
// ---------------------------------------------------------------------------
__device__ __forceinline__ uint32_t smem_u32(const void* p) {
    uint32_t a;
    asm("{ .reg .u64 t; cvta.to.shared.u64 t, %1; cvt.u32.u64 %0, t; }"
        : "=r"(a) : "l"(p));
    return a;
}
__device__ __forceinline__ void ldm_x4(uint32_t* r, uint32_t addr) {
    asm volatile("ldmatrix.sync.aligned.m8n8.x4.shared.b16 {%0,%1,%2,%3}, [%4];"
                 : "=r"(r[0]), "=r"(r[1]), "=r"(r[2]), "=r"(r[3]) : "r"(addr));
}
__device__ __forceinline__ void ldm_x4_t(uint32_t* r, uint32_t addr) {
    asm volatile("ldmatrix.sync.aligned.m8n8.x4.trans.shared.b16 {%0,%1,%2,%3}, [%4];"
                 : "=r"(r[0]), "=r"(r[1]), "=r"(r[2]), "=r"(r[3]) : "r"(addr));
}
__device__ __forceinline__ void mma16816(float* c, const uint32_t* a,
                                         uint32_t b0, uint32_t b1) {
    asm volatile(
        "mma.sync.aligned.m16n8k16.row.col.f32.bf16.bf16.f32 "
        "{%0,%1,%2,%3}, {%4,%5,%6,%7}, {%8,%9}, {%0,%1,%2,%3};"
        : "+f"(c[0]), "+f"(c[1]), "+f"(c[2]), "+f"(c[3])
        : "r"(a[0]), "r"(a[1]), "r"(a[2]), "r"(a[3]), "r"(b0), "r"(b1));
}
__device__ __forceinline__ void cp_async16(uint32_t saddr, const void* gaddr) {
    asm volatile("cp.async.cg.shared.global [%0], [%1], 16;"
                 :: "r"(saddr), "l"(gaddr));
}
#define CP_COMMIT() asm volatile("cp.async.commit_group;" ::: "memory")
#define CP_WAIT2()  asm volatile("cp.async.wait_group 2;" ::: "memory")

// FMA-pipe exp: 2^y with y = x*log2e, y <= 0 (avoids the MUFU bottleneck)
__device__ __forceinline__ float exp2p(float y) {
    y = fmaxf(y, -126.0f);                       // -inf masks -> ~0
    float t = y + 12582912.0f;                   // 1.5*2^23: round-to-int
    int n = __float_as_int(t) - 0x4B400000;
    float f = y - (t - 12582912.0f);             // f in [-0.5, 0.5]
    float p = 0.0013333558f;
    p = fmaf(p, f, 0.0096181291f);
    p = fmaf(p, f, 0.0555041087f);
    p = fmaf(p, f, 0.2402265070f);
    p = fmaf(p, f, 0.6931471806f);
    p = fmaf(p, f, 1.0f);
    return __int_as_float(__float_as_int(p) + (n << 23));
}

// ---------------------------------------------------------------------------
// Split pre-pass kernels: fp32 -> bf16 hi/lo
// ---------------------------------------------------------------------------
__global__ __launch_bounds__(256) void split_x(const float* __restrict__ x) {
    size_t i = ((size_t)blockIdx.x * 256 + threadIdx.x) * 4;
    float4 v = *(const float4*)(x + i);
    __nv_bfloat16 h0 = __float2bfloat16(v.x), h1 = __float2bfloat16(v.y);
    __nv_bfloat16 h2 = __float2bfloat16(v.z), h3 = __float2bfloat16(v.w);
    __nv_bfloat16 l0 = __float2bfloat16(v.x - __bfloat162float(h0));
    __nv_bfloat16 l1 = __float2bfloat16(v.y - __bfloat162float(h1));
    __nv_bfloat16 l2 = __float2bfloat16(v.z - __bfloat162float(h2));
    __nv_bfloat16 l3 = __float2bfloat16(v.w - __bfloat162float(h3));
    *(ushort4*)(g_xhi + i) = make_ushort4(
        __bfloat16_as_ushort(h0), __bfloat16_as_ushort(h1),
        __bfloat16_as_ushort(h2), __bfloat16_as_ushort(h3));
    *(ushort4*)(g_xlo + i) = make_ushort4(
        __bfloat16_as_ushort(l0), __bfloat16_as_ushort(l1),
        __bfloat16_as_ushort(l2), __bfloat16_as_ushort(l3));
}

__global__ __launch_bounds__(256) void split_wt(const float* __restrict__ w) {
    const int n = blockIdx.x;
    const int k0 = threadIdx.x * 4;
    float v[4];
#pragma unroll
    for (int j = 0; j < 4; j++) v[j] = w[(size_t)(k0 + j) * N_TOT + n];
    unsigned short hh[4], ll[4];
#pragma unroll
    for (int j = 0; j < 4; j++) {
        __nv_bfloat16 h = __float2bfloat16(v[j]);
        __nv_bfloat16 l = __float2bfloat16(v[j] - __bfloat162float(h));
        hh[j] = __bfloat16_as_ushort(h);
        ll[j] = __bfloat16_as_ushort(l);
    }
    *(ushort4*)(g_wthi + (size_t)n * K_TOT + k0) = make_ushort4(hh[0], hh[1], hh[2], hh[3]);
    *(ushort4*)(g_wtlo + (size_t)n * K_TOT + k0) = make_ushort4(ll[0], ll[1], ll[2], ll[3]);
}

// ---------------------------------------------------------------------------
// QKV GEMM via mma.sync bf16 split (D = Ah.Bh + Ah.Bl + Al.Bh, fp32 accum).
// Epilogue writes Q/K/V directly as bf16 hi/lo pairs in [B,H,S,D].
// ---------------------------------------------------------------------------
#define BKC    64
#define NCHUNK (K_TOT / BKC)     // 16
#define OPBYTES (128 * 128)
#define STB    (4 * OPBYTES)
#define GSM    (3 * STB)         // 196608

__global__ __launch_bounds__(256, 1) void qkv_mma() {
    extern __shared__ char sm[];
    const int tid = threadIdx.x;
    const int lane = tid & 31;
    const int w = tid >> 5;
    const int wr = w & 3, wc = w >> 2;
    const int wm0 = wr * 32, wn0 = wc * 64;
    const int m0 = (int)blockIdx.y << 7;
    const int n0 = (int)blockIdx.x << 7;
    const uint32_t smb = smem_u32(sm);

    const __nv_bfloat16* srcs[4] = {
        g_xhi + (size_t)m0 * K_TOT, g_xlo + (size_t)m0 * K_TOT,
        g_wthi + (size_t)n0 * K_TOT, g_wtlo + (size_t)n0 * K_TOT };

    auto issue_stage = [&](int buf, int kc) {
        const int koff = kc * BKC;
#pragma unroll
        for (int op = 0; op < 4; op++) {
            const uint32_t sb = smb + buf * STB + op * OPBYTES;
            const __nv_bfloat16* gp = srcs[op] + koff;
#pragma unroll
            for (int t = 0; t < 4; t++) {
                const int idx = tid + t * 256;
                const int row = idx >> 3, seg = idx & 7;
                uint32_t off = (uint32_t)(row * 128 + seg * 16);
                off ^= (off >> 3) & 0x70;
                cp_async16(sb + off, gp + (size_t)row * K_TOT + seg * 8);
            }
        }
    };

    float acc[2][8][4];
#pragma unroll
    for (int i = 0; i < 2; i++)
#pragma unroll
        for (int j = 0; j < 8; j++)
#pragma unroll
            for (int q = 0; q < 4; q++) acc[i][j][q] = 0.0f;

    issue_stage(0, 0); CP_COMMIT();
    issue_stage(1, 1); CP_COMMIT();

    for (int c = 0; c < NCHUNK; c++) {
        if (c + 2 < NCHUNK) issue_stage((c + 2) % 3, c + 2);
        CP_COMMIT();
        CP_WAIT2();
        __syncthreads();

        const uint32_t ab = smb + (c % 3) * STB;
        const uint32_t alb = ab + OPBYTES;
        const uint32_t bhb = ab + 2 * OPBYTES;
        const uint32_t blb = ab + 3 * OPBYTES;

#pragma unroll
        for (int ks = 0; ks < 4; ks++) {
            uint32_t ah[2][4], al[2][4];
#pragma unroll
            for (int mi = 0; mi < 2; mi++) {
                const int row = wm0 + mi * 16 + (lane & 15);
                const int seg = ks * 2 + (lane >> 4);
                const uint32_t off = row * 128 + (((seg ^ (row & 7)) & 7) << 4);
                ldm_x4(ah[mi], ab + off);
                ldm_x4(al[mi], alb + off);
            }
            uint32_t bh[4][4], bl[4][4];
#pragma unroll
            for (int nf = 0; nf < 4; nf++) {
                const int row = wn0 + nf * 16 + (lane & 7) + ((lane >> 4) << 3);
                const int seg = ks * 2 + ((lane >> 3) & 1);
                const uint32_t off = row * 128 + (((seg ^ (row & 7)) & 7) << 4);
                ldm_x4(bh[nf], bhb + off);
                ldm_x4(bl[nf], blb + off);
            }
#pragma unroll
            for (int mi = 0; mi < 2; mi++)
#pragma unroll
                for (int nf = 0; nf < 4; nf++) {
                    mma16816(acc[mi][2 * nf],     ah[mi], bh[nf][0], bh[nf][1]);
                    mma16816(acc[mi][2 * nf + 1], ah[mi], bh[nf][2], bh[nf][3]);
                    mma16816(acc[mi][2 * nf],     ah[mi], bl[nf][0], bl[nf][1]);
                    mma16816(acc[mi][2 * nf + 1], ah[mi], bl[nf][2], bl[nf][3]);
                    mma16816(acc[mi][2 * nf],     al[mi], bh[nf][0], bh[nf][1]);
                    mma16816(acc[mi][2 * nf + 1], al[mi], bh[nf][2], bh[nf][3]);
                }
        }
        __syncthreads();
    }

    // epilogue: split each fp32 result to bf16 hi/lo, scatter to [B,H,S,D]
    const int qr = lane >> 2;
    const int qc = (lane & 3) << 1;
    const int bb = m0 >> 11;
    const int ncol0 = n0 + wn0;
    const int which = ncol0 >> 10;
    const int h = (ncol0 >> 6) & (NH - 1);
    const size_t hoff = ((size_t)(bb * NH + h)) * S_LEN * HD;
    __nv_bfloat16* hbase = (which == 0 ? g_qhi : which == 1 ? g_khi : g_vhi) + hoff;
    __nv_bfloat16* lbase = (which == 0 ? g_qlo : which == 1 ? g_klo : g_vlo) + hoff;
    const float sc = (which == 0) ? 0.125f : 1.0f;   // fold 1/sqrt(D) into Q
    const int s00 = (m0 & (S_LEN - 1)) + wm0;

#pragma unroll
    for (int mi = 0; mi < 2; mi++)
#pragma unroll
        for (int nf8 = 0; nf8 < 8; nf8++) {
            const int d = nf8 * 8 + qc;
            const int s0 = s00 + mi * 16 + qr;
#pragma unroll
            for (int rr = 0; rr < 2; rr++) {
                const float v0 = acc[mi][nf8][2 * rr + 0] * sc;
                const float v1 = acc[mi][nf8][2 * rr + 1] * sc;
                __nv_bfloat162 h2 = __floats2bfloat162_rn(v0, v1);
                float2 hf = __bfloat1622float2(h2);
                __nv_bfloat162 l2 = __floats2bfloat162_rn(v0 - hf.x, v1 - hf.y);
                const size_t idx = (size_t)(s0 + 8 * rr) * HD + d;
                *(__nv_bfloat162*)(hbase + idx) = h2;
                *(__nv_bfloat162*)(lbase + idx) = l2;
            }
        }
}

// ---------------------------------------------------------------------------
// Flash attention on mma.sync bf16 split + FMA-pipe softmax.
// CTA = 128 Q rows x 64 KV tile, 8 warps (16 Q rows each), 3-stage cp.async.
// smem: Qhi 16K | Qlo 16K | 3 x (Khi 8K | Klo 8K | Vhi 8K | Vlo 8K)
// ---------------------------------------------------------------------------
#define AT_STG 32768
#define AT_SMEM (32768 + 3 * AT_STG)   // 131072

__global__ __launch_bounds__(256, 1) void attn_mma(float* __restrict__ out) {
    extern __shared__ char smx[];
    const int tid = threadIdx.x, lane = tid & 31, w = tid >> 5;
    const int qt = (int)gridDim.x - 1 - (int)blockIdx.x;  // long CTAs first
    const int bh = blockIdx.y;
    const int qbase = qt << 7;
    const int nk = 2 * qt + 2;
    const uint32_t smb = smem_u32(smx);
    const uint32_t QH = smb, QL = smb + 16384;
    const uint32_t ST0 = smb + 32768;
    const float NEG_INF = __int_as_float(0xff800000);

    const size_t hoff = (size_t)bh * S_LEN * HD;
    const __nv_bfloat16* qhg = g_qhi + hoff + (size_t)qbase * HD;
    const __nv_bfloat16* qlg = g_qlo + hoff + (size_t)qbase * HD;
    const __nv_bfloat16* khg = g_khi + hoff;
    const __nv_bfloat16* klg = g_klo + hoff;
    const __nv_bfloat16* vhg = g_vhi + hoff;
    const __nv_bfloat16* vlg = g_vlo + hoff;

    // ---- Q load (once): 2 arrays x 128 rows x 8 segs ----
#pragma unroll
    for (int t = 0; t < 4; t++) {
        const int idx = tid + t * 256;
        const int row = idx >> 3, seg = idx & 7;
        const uint32_t off = row * 128 + (((seg ^ (row & 7)) & 7) << 4);
        cp_async16(QH + off, qhg + (size_t)row * HD + seg * 8);
        cp_async16(QL + off, qlg + (size_t)row * HD + seg * 8);
    }

    auto issue_kv = [&](int buf, int kc) {
        const size_t koff = (size_t)kc * 64 * HD;
        const __nv_bfloat16* gps[4] = { khg + koff, klg + koff,
                                        vhg + koff, vlg + koff };
#pragma unroll
        for (int op = 0; op < 4; op++) {
            const uint32_t sb = ST0 + buf * AT_STG + op * 8192;
#pragma unroll
            for (int t = 0; t < 2; t++) {
                const int idx = tid + t * 256;
                const int row = idx >> 3, seg = idx & 7;
                const uint32_t off = row * 128 + (((seg ^ (row & 7)) & 7) << 4);
                cp_async16(sb + off, gps[op] + (size_t)row * HD + seg * 8);
            }
        }
    };

    issue_kv(0, 0); CP_COMMIT();            // group 0: Q + stage 0
    if (nk > 1) issue_kv(1, 1);
    CP_COMMIT();                             // group 1: stage 1

    // persistent state (per lane: 2 row-groups r and r+8)
    float o[8][4];
#pragma unroll
    for (int i = 0; i < 8; i++)
#pragma unroll
        for (int j = 0; j < 4; j++) o[i][j] = 0.0f;
    float m0 = NEG_INF, m1 = NEG_INF, l0 = 0.0f, l1 = 0.0f;

    const int wq0 = qbase + w * 16;          // warp's first Q row (global)
    const int r0g = wq0 + (lane >> 2);
    const int r1g = r0g + 8;

    for (int c = 0; c < nk; c++) {
        if (c + 2 < nk) issue_kv((c + 2) % 3, c + 2);
        CP_COMMIT();
        CP_WAIT2();
        __syncthreads();

        const int kbase = c * 64;
        const bool active = (kbase <= wq0 + 15);

        if (active) {
            const uint32_t KHB = ST0 + (c % 3) * AT_STG;
            const uint32_t KLB = KHB + 8192;
            const uint32_t VHB = KHB + 16384;
            const uint32_t VLB = KHB + 24576;

            // ---- S = Q K^T (split, 3 terms) ----
            float s[8][4];
#pragma unroll
            for (int i = 0; i < 8; i++)
#pragma unroll
                for (int j = 0; j < 4; j++) s[i][j] = 0.0f;

#pragma unroll
            for (int ks = 0; ks < 4; ks++) {
                uint32_t qh[4], ql[4];
                {
                    const int row = w * 16 + (lane & 15);
                    const int seg = ks * 2 + (lane >> 4);
                    const uint32_t off = row * 128 + (((seg ^ (row & 7)) & 7) << 4);
                    ldm_x4(qh, QH + off);
                    ldm_x4(ql, QL + off);
                }
#pragma unroll
                for (int ng = 0; ng < 4; ng++) {
                    uint32_t kh[4], kl[4];
                    const int row = ng * 16 + (lane & 7) + ((lane >> 4) << 3);
                    const int seg = ks * 2 + ((lane >> 3) & 1);
                    const uint32_t off = row * 128 + (((seg ^ (row & 7)) & 7) << 4);
                    ldm_x4(kh, KHB + off);
                    ldm_x4(kl, KLB + off);
                    mma16816(s[2 * ng],     qh, kh[0], kh[1]);
                    mma16816(s[2 * ng + 1], qh, kh[2], kh[3]);
                    mma16816(s[2 * ng],     qh, kl[0], kl[1]);
                    mma16816(s[2 * ng + 1], qh, kl[2], kl[3]);
                    mma16816(s[2 * ng],     ql, kh[0], kh[1]);
                    mma16816(s[2 * ng + 1], ql, kh[2], kh[3]);
                }
            }

            // ---- causal mask ----
            if (kbase + 63 > wq0) {
#pragma unroll
                for (int nf = 0; nf < 8; nf++) {
                    const int cg = kbase + nf * 8 + ((lane & 3) << 1);
                    if (cg > r0g)     s[nf][0] = NEG_INF;
                    if (cg + 1 > r0g) s[nf][1] = NEG_INF;
                    if (cg > r1g)     s[nf][2] = NEG_INF;
                    if (cg + 1 > r1g) s[nf][3] = NEG_INF;
                }
            }

            // ---- online softmax (poly exp on FMA pipe) ----
            float mx0 = NEG_INF, mx1 = NEG_INF;
#pragma unroll
            for (int nf = 0; nf < 8; nf++) {
                mx0 = fmaxf(mx0, fmaxf(s[nf][0], s[nf][1]));
                mx1 = fmaxf(mx1, fmaxf(s[nf][2], s[nf][3]));
            }
            mx0 = fmaxf(mx0, __shfl_xor_sync(0xffffffffu, mx0, 1));
            mx0 = fmaxf(mx0, __shfl_xor_sync(0xffffffffu, mx0, 2));
            mx1 = fmaxf(mx1, __shfl_xor_sync(0xffffffffu, mx1, 1));
            mx1 = fmaxf(mx1, __shfl_xor_sync(0xffffffffu, mx1, 2));
            const float mn0 = fmaxf(m0, mx0), mn1 = fmaxf(m1, mx1);
            const float mn0L = mn0 * LOG2E, mn1L = mn1 * LOG2E;
            const float a0 = exp2p(fmaf(m0, LOG2E, -mn0L));
            const float a1 = exp2p(fmaf(m1, LOG2E, -mn1L));
            m0 = mn0; m1 = mn1;

            uint32_t ph2[8][2], pl2[8][2];
            float ps0 = 0.0f, ps1 = 0.0f;
#pragma unroll
            for (int nf = 0; nf < 8; nf++) {
                const float p0 = exp2p(fmaf(s[nf][0], LOG2E, -mn0L));
                const float p1 = exp2p(fmaf(s[nf][1], LOG2E, -mn0L));
                const float p2 = exp2p(fmaf(s[nf][2], LOG2E, -mn1L));
                const float p3 = exp2p(fmaf(s[nf][3], LOG2E, -mn1L));
                ps0 += p0 + p1; ps1 += p2 + p3;
                __nv_bfloat162 h01 = __floats2bfloat162_rn(p0, p1);
                __nv_bfloat162 h23 = __floats2bfloat162_rn(p2, p3);
                float2 f01 = __bfloat1622float2(h01);
                float2 f23 = __bfloat1622float2(h23);
                __nv_bfloat162 l01 = __floats2bfloat162_rn(p0 - f01.x, p1 - f01.y);
                __nv_bfloat162 l23 = __floats2bfloat162_rn(p2 - f23.x, p3 - f23.y);
                ph2[nf][0] = *(uint32_t*)&h01; ph2[nf][1] = *(uint32_t*)&h23;
                pl2[nf][0] = *(uint32_t*)&l01; pl2[nf][1] = *(uint32_t*)&l23;
            }
            ps0 += __shfl_xor_sync(0xffffffffu, ps0, 1);
            ps0 += __shfl_xor_sync(0xffffffffu, ps0, 2);
            ps1 += __shfl_xor_sync(0xffffffffu, ps1, 1);
            ps1 += __shfl_xor_sync(0xffffffffu, ps1, 2);
            l0 = fmaf(l0, a0, ps0);
            l1 = fmaf(l1, a1, ps1);
#pragma unroll
            for (int nf = 0; nf < 8; nf++) {
                o[nf][0] *= a0; o[nf][1] *= a0;
                o[nf][2] *= a1; o[nf][3] *= a1;
            }

            // ---- O += P V (split, 3 terms) ----
#pragma unroll
            for (int ks = 0; ks < 4; ks++) {
                uint32_t ah[4] = { ph2[2 * ks][0], ph2[2 * ks][1],
                                   ph2[2 * ks + 1][0], ph2[2 * ks + 1][1] };
                uint32_t al[4] = { pl2[2 * ks][0], pl2[2 * ks][1],
                                   pl2[2 * ks + 1][0], pl2[2 * ks + 1][1] };
#pragma unroll
                for (int ng = 0; ng < 4; ng++) {
                    uint32_t vh[4], vl[4];
                    const int row = ks * 16 + (lane & 15);
                    const int seg = ng * 2 + (lane >> 4);
                    const uint32_t off = row * 128 + (((seg ^ (row & 7)) & 7) << 4);
                    ldm_x4_t(vh, VHB + off);
                    ldm_x4_t(vl, VLB + off);
                    mma16816(o[2 * ng],     ah, vh[0], vh[1]);
                    mma16816(o[2 * ng + 1], ah, vh[2], vh[3]);
                    mma16816(o[2 * ng],     ah, vl[0], vl[1]);
                    mma16816(o[2 * ng + 1], ah, vl[2], vl[3]);
                    mma16816(o[2 * ng],     al, vh[0], vh[1]);
                    mma16816(o[2 * ng + 1], al, vh[2], vh[3]);
                }
            }
        }
        __syncthreads();
    }

    // ---- final write: out[b, s, h*64 + d] ----
    const int b = bh >> 4, h = bh & 15;
    const float inv0 = 1.0f / l0, inv1 = 1.0f / l1;
#pragma unroll
    for (int nf = 0; nf < 8; nf++) {
        const int d = h * HD + nf * 8 + ((lane & 3) << 1);
        float2 u0 = make_float2(o[nf][0] * inv0, o[nf][1] * inv0);
        float2 u1 = make_float2(o[nf][2] * inv1, o[nf][3] * inv1);
        *(float2*)(out + ((size_t)b * S_LEN + r0g) * E_DIM + d) = u0;
        *(float2*)(out + ((size_t)b * S_LEN + r1g) * E_DIM + d) = u1;
    }
}

// ============================================================================
// Launch
// ============================================================================
extern "C" void kernel_launch(void* const* d_in, const int* in_sizes, int n_in,
                              void* d_out, int out_size) {
    (void)in_sizes; (void)n_in; (void)out_size;
    const float* x = (const float*)d_in[0];   // [4,2048,1024] fp32
    const float* w = (const float*)d_in[1];   // [1024,3072] fp32
    float* out = (float*)d_out;               // [4,2048,1024] fp32

    static int smem_set = 0;
    if (!smem_set) {
        cudaFuncSetAttribute(qkv_mma,
                             cudaFuncAttributeMaxDynamicSharedMemorySize, GSM);
        cudaFuncSetAttribute(attn_mma,
                             cudaFuncAttributeMaxDynamicSharedMemorySize, AT_SMEM);
        smem_set = 1;
    }

    split_x<<<(size_t)M_TOT * K_TOT / 4 / 256, 256>>>(x);
    split_wt<<<N_TOT, 256>>>(w);
    qkv_mma<<<dim3(N_TOT / 128, M_TOT / 128), 256, GSM>>>();
    attn_mma<<<dim3(S_LEN / 128, B_SZ * NH), 256, AT_SMEM>>>(out);
}

// round 17
// speedup vs baseline: 3.0189x; 1.0010x over previous
#include <cuda_runtime.h>
#include <cuda_bf16.h>
#include <cstdint>
#include <cstddef>

// Problem constants
#define B_SZ  4
#define S_LEN 2048
#define E_DIM 1024
#define NH    16
#define HD    64
#define M_TOT (B_SZ * S_LEN)   // 8192
#define N_TOT (3 * E_DIM)      // 3072
#define K_TOT E_DIM            // 1024

#define LOG2E 1.4426950408889634f

// ---------------------------------------------------------------------------
// Device-global scratch (no runtime allocation allowed)
// Q/K/V stored as bf16 hi/lo split pairs, [B,H,S,D] layout.
// ---------------------------------------------------------------------------
__device__ __nv_bfloat16 g_qhi[(size_t)B_SZ * NH * S_LEN * HD];
__device__ __nv_bfloat16 g_qlo[(size_t)B_SZ * NH * S_LEN * HD];
__device__ __nv_bfloat16 g_khi[(size_t)B_SZ * NH * S_LEN * HD];
__device__ __nv_bfloat16 g_klo[(size_t)B_SZ * NH * S_LEN * HD];
__device__ __nv_bfloat16 g_vhi[(size_t)B_SZ * NH * S_LEN * HD];
__device__ __nv_bfloat16 g_vlo[(size_t)B_SZ * NH * S_LEN * HD];

// bf16 hi/lo splits of GEMM inputs: x as [M,K], W^T as [N,K]
__device__ __nv_bfloat16 g_xhi[(size_t)M_TOT * K_TOT];
__device__ __nv_bfloat16 g_xlo[(size_t)M_TOT * K_TOT];
__device__ __nv_bfloat16 g_wthi[(size_t)N_TOT * K_TOT];
__device__ __nv_bfloat16 g_wtlo[(size_t)N_TOT * K_TOT];

// ---------------------------------------------------------------------------
// mma.sync / ldmatrix / cp.async helpers (baseline PTX, valid on sm_103)
// ---------------------------------------------------------------------------
__device__ __forceinline__ uint32_t smem_u32(const void* p) {
    uint32_t a;
    asm("{ .reg .u64 t; cvta.to.shared.u64 t, %1; cvt.u32.u64 %0, t; }"
        : "=r"(a) : "l"(p));
    return a;
}
__device__ __forceinline__ void ldm_x4(uint32_t* r, uint32_t addr) {
    asm volatile("ldmatrix.sync.aligned.m8n8.x4.shared.b16 {%0,%1,%2,%3}, [%4];"
                 : "=r"(r[0]), "=r"(r[1]), "=r"(r[2]), "=r"(r[3]) : "r"(addr));
}
__device__ __forceinline__ void ldm_x4_t(uint32_t* r, uint32_t addr) {
    asm volatile("ldmatrix.sync.aligned.m8n8.x4.trans.shared.b16 {%0,%1,%2,%3}, [%4];"
                 : "=r"(r[0]), "=r"(r[1]), "=r"(r[2]), "=r"(r[3]) : "r"(addr));
}
__device__ __forceinline__ void mma16816(float* c, const uint32_t* a,
                                         uint32_t b0, uint32_t b1) {
    asm volatile(
        "mma.sync.aligned.m16n8k16.row.col.f32.bf16.bf16.f32 "
        "{%0,%1,%2,%3}, {%4,%5,%6,%7}, {%8,%9}, {%0,%1,%2,%3};"
        : "+f"(c[0]), "+f"(c[1]), "+f"(c[2]), "+f"(c[3])
        : "r"(a[0]), "r"(a[1]), "r"(a[2]), "r"(a[3]), "r"(b0), "r"(b1));
}
__device__ __forceinline__ void cp_async16(uint32_t saddr, const void* gaddr) {
    asm volatile("cp.async.cg.shared.global [%0], [%1], 16;"
                 :: "r"(saddr), "l"(gaddr));
}
#define CP_COMMIT() asm volatile("cp.async.commit_group;" ::: "memory")
#define CP_WAIT2()  asm volatile("cp.async.wait_group 2;" ::: "memory")

// FMA-pipe exp: 2^y with y = x*log2e, y <= 0 (avoids the MUFU bottleneck)
__device__ __forceinline__ float exp2p(float y) {
    y = fmaxf(y, -126.0f);                       // -inf masks -> ~0
    float t = y + 12582912.0f;                   // 1.5*2^23: round-to-int
    int n = __float_as_int(t) - 0x4B400000;
    float f = y - (t - 12582912.0f);             // f in [-0.5, 0.5]
    float p = 0.0013333558f;
    p = fmaf(p, f, 0.0096181291f);
    p = fmaf(p, f, 0.0555041087f);
    p = fmaf(p, f, 0.2402265070f);
    p = fmaf(p, f, 0.6931471806f);
    p = fmaf(p, f, 1.0f);
    return __int_as_float(__float_as_int(p) + (n << 23));
}

// ---------------------------------------------------------------------------
// Split pre-pass kernels: fp32 -> bf16 hi/lo
// ---------------------------------------------------------------------------
__global__ __launch_bounds__(256) void split_x(const float* __restrict__ x) {
    size_t i = ((size_t)blockIdx.x * 256 + threadIdx.x) * 4;
    float4 v = *(const float4*)(x + i);
    __nv_bfloat16 h0 = __float2bfloat16(v.x), h1 = __float2bfloat16(v.y);
    __nv_bfloat16 h2 = __float2bfloat16(v.z), h3 = __float2bfloat16(v.w);
    __nv_bfloat16 l0 = __float2bfloat16(v.x - __bfloat162float(h0));
    __nv_bfloat16 l1 = __float2bfloat16(v.y - __bfloat162float(h1));
    __nv_bfloat16 l2 = __float2bfloat16(v.z - __bfloat162float(h2));
    __nv_bfloat16 l3 = __float2bfloat16(v.w - __bfloat162float(h3));
    *(ushort4*)(g_xhi + i) = make_ushort4(
        __bfloat16_as_ushort(h0), __bfloat16_as_ushort(h1),
        __bfloat16_as_ushort(h2), __bfloat16_as_ushort(h3));
    *(ushort4*)(g_xlo + i) = make_ushort4(
        __bfloat16_as_ushort(l0), __bfloat16_as_ushort(l1),
        __bfloat16_as_ushort(l2), __bfloat16_as_ushort(l3));
}

__global__ __launch_bounds__(256) void split_wt(const float* __restrict__ w) {
    const int n = blockIdx.x;
    const int k0 = threadIdx.x * 4;
    float v[4];
#pragma unroll
    for (int j = 0; j < 4; j++) v[j] = w[(size_t)(k0 + j) * N_TOT + n];
    unsigned short hh[4], ll[4];
#pragma unroll
    for (int j = 0; j < 4; j++) {
        __nv_bfloat16 h = __float2bfloat16(v[j]);
        __nv_bfloat16 l = __float2bfloat16(v[j] - __bfloat162float(h));
        hh[j] = __bfloat16_as_ushort(h);
        ll[j] = __bfloat16_as_ushort(l);
    }
    *(ushort4*)(g_wthi + (size_t)n * K_TOT + k0) = make_ushort4(hh[0], hh[1], hh[2], hh[3]);
    *(ushort4*)(g_wtlo + (size_t)n * K_TOT + k0) = make_ushort4(ll[0], ll[1], ll[2], ll[3]);
}

// ---------------------------------------------------------------------------
// QKV GEMM via mma.sync bf16 split (D = Ah.Bh + Ah.Bl + Al.Bh, fp32 accum).
// Epilogue writes Q/K/V directly as bf16 hi/lo pairs in [B,H,S,D].
// ---------------------------------------------------------------------------
#define BKC    64
#define NCHUNK (K_TOT / BKC)     // 16
#define OPBYTES (128 * 128)
#define STB    (4 * OPBYTES)
#define GSM    (3 * STB)         // 196608

__global__ __launch_bounds__(256, 1) void qkv_mma() {
    extern __shared__ char sm[];
    const int tid = threadIdx.x;
    const int lane = tid & 31;
    const int w = tid >> 5;
    const int wr = w & 3, wc = w >> 2;
    const int wm0 = wr * 32, wn0 = wc * 64;
    const int m0 = (int)blockIdx.y << 7;
    const int n0 = (int)blockIdx.x << 7;
    const uint32_t smb = smem_u32(sm);

    const __nv_bfloat16* srcs[4] = {
        g_xhi + (size_t)m0 * K_TOT, g_xlo + (size_t)m0 * K_TOT,
        g_wthi + (size_t)n0 * K_TOT, g_wtlo + (size_t)n0 * K_TOT };

    auto issue_stage = [&](int buf, int kc) {
        const int koff = kc * BKC;
#pragma unroll
        for (int op = 0; op < 4; op++) {
            const uint32_t sb = smb + buf * STB + op * OPBYTES;
            const __nv_bfloat16* gp = srcs[op] + koff;
#pragma unroll
            for (int t = 0; t < 4; t++) {
                const int idx = tid + t * 256;
                const int row = idx >> 3, seg = idx & 7;
                uint32_t off = (uint32_t)(row * 128 + seg * 16);
                off ^= (off >> 3) & 0x70;
                cp_async16(sb + off, gp + (size_t)row * K_TOT + seg * 8);
            }
        }
    };

    float acc[2][8][4];
#pragma unroll
    for (int i = 0; i < 2; i++)
#pragma unroll
        for (int j = 0; j < 8; j++)
#pragma unroll
            for (int q = 0; q < 4; q++) acc[i][j][q] = 0.0f;

    issue_stage(0, 0); CP_COMMIT();
    issue_stage(1, 1); CP_COMMIT();

    for (int c = 0; c < NCHUNK; c++) {
        if (c + 2 < NCHUNK) issue_stage((c + 2) % 3, c + 2);
        CP_COMMIT();
        CP_WAIT2();
        __syncthreads();

        const uint32_t ab = smb + (c % 3) * STB;
        const uint32_t alb = ab + OPBYTES;
        const uint32_t bhb = ab + 2 * OPBYTES;
        const uint32_t blb = ab + 3 * OPBYTES;

#pragma unroll
        for (int ks = 0; ks < 4; ks++) {
            uint32_t ah[2][4], al[2][4];
#pragma unroll
            for (int mi = 0; mi < 2; mi++) {
                const int row = wm0 + mi * 16 + (lane & 15);
                const int seg = ks * 2 + (lane >> 4);
                const uint32_t off = row * 128 + (((seg ^ (row & 7)) & 7) << 4);
                ldm_x4(ah[mi], ab + off);
                ldm_x4(al[mi], alb + off);
            }
            uint32_t bh[4][4], bl[4][4];
#pragma unroll
            for (int nf = 0; nf < 4; nf++) {
                const int row = wn0 + nf * 16 + (lane & 7) + ((lane >> 4) << 3);
                const int seg = ks * 2 + ((lane >> 3) & 1);
                const uint32_t off = row * 128 + (((seg ^ (row & 7)) & 7) << 4);
                ldm_x4(bh[nf], bhb + off);
                ldm_x4(bl[nf], blb + off);
            }
#pragma unroll
            for (int mi = 0; mi < 2; mi++)
#pragma unroll
                for (int nf = 0; nf < 4; nf++) {
                    mma16816(acc[mi][2 * nf],     ah[mi], bh[nf][0], bh[nf][1]);
                    mma16816(acc[mi][2 * nf + 1], ah[mi], bh[nf][2], bh[nf][3]);
                    mma16816(acc[mi][2 * nf],     ah[mi], bl[nf][0], bl[nf][1]);
                    mma16816(acc[mi][2 * nf + 1], ah[mi], bl[nf][2], bl[nf][3]);
                    mma16816(acc[mi][2 * nf],     al[mi], bh[nf][0], bh[nf][1]);
                    mma16816(acc[mi][2 * nf + 1], al[mi], bh[nf][2], bh[nf][3]);
                }
        }
        __syncthreads();
    }

    // epilogue: split each fp32 result to bf16 hi/lo, scatter to [B,H,S,D]
    const int qr = lane >> 2;
    const int qc = (lane & 3) << 1;
    const int bb = m0 >> 11;
    const int ncol0 = n0 + wn0;
    const int which = ncol0 >> 10;
    const int h = (ncol0 >> 6) & (NH - 1);
    const size_t hoff = ((size_t)(bb * NH + h)) * S_LEN * HD;
    __nv_bfloat16* hbase = (which == 0 ? g_qhi : which == 1 ? g_khi : g_vhi) + hoff;
    __nv_bfloat16* lbase = (which == 0 ? g_qlo : which == 1 ? g_klo : g_vlo) + hoff;
    const float sc = (which == 0) ? 0.125f : 1.0f;   // fold 1/sqrt(D) into Q
    const int s00 = (m0 & (S_LEN - 1)) + wm0;

#pragma unroll
    for (int mi = 0; mi < 2; mi++)
#pragma unroll
        for (int nf8 = 0; nf8 < 8; nf8++) {
            const int d = nf8 * 8 + qc;
            const int s0 = s00 + mi * 16 + qr;
#pragma unroll
            for (int rr = 0; rr < 2; rr++) {
                const float v0 = acc[mi][nf8][2 * rr + 0] * sc;
                const float v1 = acc[mi][nf8][2 * rr + 1] * sc;
                __nv_bfloat162 h2 = __floats2bfloat162_rn(v0, v1);
                float2 hf = __bfloat1622float2(h2);
                __nv_bfloat162 l2 = __floats2bfloat162_rn(v0 - hf.x, v1 - hf.y);
                const size_t idx = (size_t)(s0 + 8 * rr) * HD + d;
                *(__nv_bfloat162*)(hbase + idx) = h2;
                *(__nv_bfloat162*)(lbase + idx) = l2;
            }
        }
}

// ---------------------------------------------------------------------------
// Flash attention on mma.sync bf16 split + FMA-pipe softmax.
// CTA = 128 Q rows x 64 KV tile, 8 warps (16 Q rows each), 3-stage cp.async.
// smem: Qhi 16K | Qlo 16K | 3 x (Khi 8K | Klo 8K | Vhi 8K | Vlo 8K)
// ---------------------------------------------------------------------------
#define AT_STG 32768
#define AT_SMEM (32768 + 3 * AT_STG)   // 131072

__global__ __launch_bounds__(256, 1) void attn_mma(float* __restrict__ out) {
    extern __shared__ char smx[];
    const int tid = threadIdx.x, lane = tid & 31, w = tid >> 5;
    const int qt = (int)gridDim.x - 1 - (int)blockIdx.x;  // long CTAs first
    const int bh = blockIdx.y;
    const int qbase = qt << 7;
    const int nk = 2 * qt + 2;
    const uint32_t smb = smem_u32(smx);
    const uint32_t QH = smb, QL = smb + 16384;
    const uint32_t ST0 = smb + 32768;
    const float NEG_INF = __int_as_float(0xff800000);

    const size_t hoff = (size_t)bh * S_LEN * HD;
    const __nv_bfloat16* qhg = g_qhi + hoff + (size_t)qbase * HD;
    const __nv_bfloat16* qlg = g_qlo + hoff + (size_t)qbase * HD;
    const __nv_bfloat16* khg = g_khi + hoff;
    const __nv_bfloat16* klg = g_klo + hoff;
    const __nv_bfloat16* vhg = g_vhi + hoff;
    const __nv_bfloat16* vlg = g_vlo + hoff;

    // ---- Q load (once): 2 arrays x 128 rows x 8 segs ----
#pragma unroll
    for (int t = 0; t < 4; t++) {
        const int idx = tid + t * 256;
        const int row = idx >> 3, seg = idx & 7;
        const uint32_t off = row * 128 + (((seg ^ (row & 7)) & 7) << 4);
        cp_async16(QH + off, qhg + (size_t)row * HD + seg * 8);
        cp_async16(QL + off, qlg + (size_t)row * HD + seg * 8);
    }

    auto issue_kv = [&](int buf, int kc) {
        const size_t koff = (size_t)kc * 64 * HD;
        const __nv_bfloat16* gps[4] = { khg + koff, klg + koff,
                                        vhg + koff, vlg + koff };
#pragma unroll
        for (int op = 0; op < 4; op++) {
            const uint32_t sb = ST0 + buf * AT_STG + op * 8192;
#pragma unroll
            for (int t = 0; t < 2; t++) {
                const int idx = tid + t * 256;
                const int row = idx >> 3, seg = idx & 7;
                const uint32_t off = row * 128 + (((seg ^ (row & 7)) & 7) << 4);
                cp_async16(sb + off, gps[op] + (size_t)row * HD + seg * 8);
            }
        }
    };

    issue_kv(0, 0); CP_COMMIT();            // group 0: Q + stage 0
    if (nk > 1) issue_kv(1, 1);
    CP_COMMIT();                             // group 1: stage 1

    // persistent state (per lane: 2 row-groups r and r+8)
    float o[8][4];
#pragma unroll
    for (int i = 0; i < 8; i++)
#pragma unroll
        for (int j = 0; j < 4; j++) o[i][j] = 0.0f;
    float m0 = NEG_INF, m1 = NEG_INF, l0 = 0.0f, l1 = 0.0f;

    const int wq0 = qbase + w * 16;          // warp's first Q row (global)
    const int r0g = wq0 + (lane >> 2);
    const int r1g = r0g + 8;

    for (int c = 0; c < nk; c++) {
        if (c + 2 < nk) issue_kv((c + 2) % 3, c + 2);
        CP_COMMIT();
        CP_WAIT2();
        __syncthreads();

        const int kbase = c * 64;
        const bool active = (kbase <= wq0 + 15);

        if (active) {
            const uint32_t KHB = ST0 + (c % 3) * AT_STG;
            const uint32_t KLB = KHB + 8192;
            const uint32_t VHB = KHB + 16384;
            const uint32_t VLB = KHB + 24576;

            // ---- S = Q K^T (split, 3 terms) ----
            float s[8][4];
#pragma unroll
            for (int i = 0; i < 8; i++)
#pragma unroll
                for (int j = 0; j < 4; j++) s[i][j] = 0.0f;

#pragma unroll
            for (int ks = 0; ks < 4; ks++) {
                uint32_t qh[4], ql[4];
                {
                    const int row = w * 16 + (lane & 15);
                    const int seg = ks * 2 + (lane >> 4);
                    const uint32_t off = row * 128 + (((seg ^ (row & 7)) & 7) << 4);
                    ldm_x4(qh, QH + off);
                    ldm_x4(ql, QL + off);
                }
#pragma unroll
                for (int ng = 0; ng < 4; ng++) {
                    uint32_t kh[4], kl[4];
                    const int row = ng * 16 + (lane & 7) + ((lane >> 4) << 3);
                    const int seg = ks * 2 + ((lane >> 3) & 1);
                    const uint32_t off = row * 128 + (((seg ^ (row & 7)) & 7) << 4);
                    ldm_x4(kh, KHB + off);
                    ldm_x4(kl, KLB + off);
                    mma16816(s[2 * ng],     qh, kh[0], kh[1]);
                    mma16816(s[2 * ng + 1], qh, kh[2], kh[3]);
                    mma16816(s[2 * ng],     qh, kl[0], kl[1]);
                    mma16816(s[2 * ng + 1], qh, kl[2], kl[3]);
                    mma16816(s[2 * ng],     ql, kh[0], kh[1]);
                    mma16816(s[2 * ng + 1], ql, kh[2], kh[3]);
                }
            }

            // ---- causal mask ----
            if (kbase + 63 > wq0) {
#pragma unroll
                for (int nf = 0; nf < 8; nf++) {
                    const int cg = kbase + nf * 8 + ((lane & 3) << 1);
                    if (cg > r0g)     s[nf][0] = NEG_INF;
                    if (cg + 1 > r0g) s[nf][1] = NEG_INF;
                    if (cg > r1g)     s[nf][2] = NEG_INF;
                    if (cg + 1 > r1g) s[nf][3] = NEG_INF;
                }
            }

            // ---- online softmax (poly exp on FMA pipe) ----
            float mx0 = NEG_INF, mx1 = NEG_INF;
#pragma unroll
            for (int nf = 0; nf < 8; nf++) {
                mx0 = fmaxf(mx0, fmaxf(s[nf][0], s[nf][1]));
                mx1 = fmaxf(mx1, fmaxf(s[nf][2], s[nf][3]));
            }
            mx0 = fmaxf(mx0, __shfl_xor_sync(0xffffffffu, mx0, 1));
            mx0 = fmaxf(mx0, __shfl_xor_sync(0xffffffffu, mx0, 2));
            mx1 = fmaxf(mx1, __shfl_xor_sync(0xffffffffu, mx1, 1));
            mx1 = fmaxf(mx1, __shfl_xor_sync(0xffffffffu, mx1, 2));
            const float mn0 = fmaxf(m0, mx0), mn1 = fmaxf(m1, mx1);
            const float mn0L = mn0 * LOG2E, mn1L = mn1 * LOG2E;
            const float a0 = exp2p(fmaf(m0, LOG2E, -mn0L));
            const float a1 = exp2p(fmaf(m1, LOG2E, -mn1L));
            m0 = mn0; m1 = mn1;

            uint32_t ph2[8][2], pl2[8][2];
            float ps0 = 0.0f, ps1 = 0.0f;
#pragma unroll
            for (int nf = 0; nf < 8; nf++) {
                const float p0 = exp2p(fmaf(s[nf][0], LOG2E, -mn0L));
                const float p1 = exp2p(fmaf(s[nf][1], LOG2E, -mn0L));
                const float p2 = exp2p(fmaf(s[nf][2], LOG2E, -mn1L));
                const float p3 = exp2p(fmaf(s[nf][3], LOG2E, -mn1L));
                ps0 += p0 + p1; ps1 += p2 + p3;
                __nv_bfloat162 h01 = __floats2bfloat162_rn(p0, p1);
                __nv_bfloat162 h23 = __floats2bfloat162_rn(p2, p3);
                float2 f01 = __bfloat1622float2(h01);
                float2 f23 = __bfloat1622float2(h23);
                __nv_bfloat162 l01 = __floats2bfloat162_rn(p0 - f01.x, p1 - f01.y);
                __nv_bfloat162 l23 = __floats2bfloat162_rn(p2 - f23.x, p3 - f23.y);
                ph2[nf][0] = *(uint32_t*)&h01; ph2[nf][1] = *(uint32_t*)&h23;
                pl2[nf][0] = *(uint32_t*)&l01; pl2[nf][1] = *(uint32_t*)&l23;
            }
            ps0 += __shfl_xor_sync(0xffffffffu, ps0, 1);
            ps0 += __shfl_xor_sync(0xffffffffu, ps0, 2);
            ps1 += __shfl_xor_sync(0xffffffffu, ps1, 1);
            ps1 += __shfl_xor_sync(0xffffffffu, ps1, 2);
            l0 = fmaf(l0, a0, ps0);
            l1 = fmaf(l1, a1, ps1);
#pragma unroll
            for (int nf = 0; nf < 8; nf++) {
                o[nf][0] *= a0; o[nf][1] *= a0;
                o[nf][2] *= a1; o[nf][3] *= a1;
            }

            // ---- O += P V (split, 3 terms) ----
#pragma unroll
            for (int ks = 0; ks < 4; ks++) {
                uint32_t ah[4] = { ph2[2 * ks][0], ph2[2 * ks][1],
                                   ph2[2 * ks + 1][0], ph2[2 * ks + 1][1] };
                uint32_t al[4] = { pl2[2 * ks][0], pl2[2 * ks][1],
                                   pl2[2 * ks + 1][0], pl2[2 * ks + 1][1] };
#pragma unroll
                for (int ng = 0; ng < 4; ng++) {
                    uint32_t vh[4], vl[4];
                    const int row = ks * 16 + (lane & 15);
                    const int seg = ng * 2 + (lane >> 4);
                    const uint32_t off = row * 128 + (((seg ^ (row & 7)) & 7) << 4);
                    ldm_x4_t(vh, VHB + off);
                    ldm_x4_t(vl, VLB + off);
                    mma16816(o[2 * ng],     ah, vh[0], vh[1]);
                    mma16816(o[2 * ng + 1], ah, vh[2], vh[3]);
                    mma16816(o[2 * ng],     ah, vl[0], vl[1]);
                    mma16816(o[2 * ng + 1], ah, vl[2], vl[3]);
                    mma16816(o[2 * ng],     al, vh[0], vh[1]);
                    mma16816(o[2 * ng + 1], al, vh[2], vh[3]);
                }
            }
        }
        __syncthreads();
    }

    // ---- final write: out[b, s, h*64 + d] ----
    const int b = bh >> 4, h = bh & 15;
    const float inv0 = 1.0f / l0, inv1 = 1.0f / l1;
#pragma unroll
    for (int nf = 0; nf < 8; nf++) {
        const int d = h * HD + nf * 8 + ((lane & 3) << 1);
        float2 u0 = make_float2(o[nf][0] * inv0, o[nf][1] * inv0);
        float2 u1 = make_float2(o[nf][2] * inv1, o[nf][3] * inv1);
        *(float2*)(out + ((size_t)b * S_LEN + r0g) * E_DIM + d) = u0;
        *(float2*)(out + ((size_t)b * S_LEN + r1g) * E_DIM + d) = u1;
    }
}

// ============================================================================
// Launch
// ============================================================================
extern "C" void kernel_launch(void* const* d_in, const int* in_sizes, int n_in,
                              void* d_out, int out_size) {
    (void)in_sizes; (void)n_in; (void)out_size;
    const float* x = (const float*)d_in[0];   // [4,2048,1024] fp32
    const float* w = (const float*)d_in[1];   // [1024,3072] fp32
    float* out = (float*)d_out;               // [4,2048,1024] fp32

    static int smem_set = 0;
    if (!smem_set) {
        cudaFuncSetAttribute(qkv_mma,
                             cudaFuncAttributeMaxDynamicSharedMemorySize, GSM);
        cudaFuncSetAttribute(attn_mma,
                             cudaFuncAttributeMaxDynamicSharedMemorySize, AT_SMEM);
        smem_set = 1;
    }

    split_x<<<(size_t)M_TOT * K_TOT / 4 / 256, 256>>>(x);
    split_wt<<<N_TOT, 256>>>(w);
    qkv_mma<<<dim3(N_TOT / 128, M_TOT / 128), 256, GSM>>>();
    attn_mma<<<dim3(S_LEN / 128, B_SZ * NH), 256, AT_SMEM>>>(out);
}